// round 3
// baseline (speedup 1.0000x reference)
#include <cuda_runtime.h>
#include <cstdint>

// Problem constants
#define NNODE 1024
#define TSTEP 32
#define HDIM  256
#define PDIM  256
#define EDIM  512
#define DTR   16
#define SDIM  16
#define NT    (NNODE * TSTEP)   // 32768

// ---------------------------------------------------------------------------
// Scratch (device globals; no dynamic allocation allowed)
// ---------------------------------------------------------------------------
__device__ float g_pe   [NNODE * PDIM];
__device__ float g_m1   [NNODE * HDIM];
__device__ float g_cbuf [(size_t)NT * 512];
__device__ float g_x    [(size_t)NT * HDIM];
__device__ float g_agg  [(size_t)NT * HDIM];
__device__ float g_m2   [(size_t)NT * HDIM];
__device__ float g_x2   [(size_t)NT * HDIM];
__device__ float g_xn   [(size_t)NT * HDIM];
__device__ float g_xp   [(size_t)NT * 1024];
__device__ float g_x1   [(size_t)NT * EDIM];
__device__ float g_delta[(size_t)NT * EDIM];
__device__ float g_d1   [(size_t)NT * DTR];
__device__ float g_Bm   [(size_t)NT * SDIM];
__device__ float g_Cm   [(size_t)NT * SDIM];
__device__ float g_y    [(size_t)NT * EDIM];
__device__ float g_mb   [(size_t)NT * HDIM];
__device__ float g_q    [(size_t)NT * HDIM];
__device__ float g_k    [(size_t)NT * HDIM];
__device__ float g_dwT  [DTR * EDIM];
__device__ float g_bwT  [DTR * EDIM];
__device__ float g_cwT  [DTR * EDIM];

// ---------------------------------------------------------------------------
// Fast math (FMA-pipe exp; avoids MUFU throughput wall: 268M exps in the scan)
// ---------------------------------------------------------------------------
__device__ __forceinline__ float fast_exp(float x) {
    x = fminf(fmaxf(x, -87.0f), 87.0f);
    float y = x * 1.44269504088896340736f;           // x * log2(e)
    float t = y + 12582912.0f;                       // round-to-nearest
    int   e = __float_as_int(t) - 0x4B400000;
    float r = t - 12582912.0f;
    float f = (y - r) * 0.69314718055994530942f;     // frac * ln2, |f|<=0.3466
    float p = 1.3888889e-3f;                          // 1/720
    p = fmaf(p, f, 8.3333333e-3f);                    // 1/120
    p = fmaf(p, f, 4.1666668e-2f);                    // 1/24
    p = fmaf(p, f, 1.6666667e-1f);                    // 1/6
    p = fmaf(p, f, 0.5f);
    p = fmaf(p, f, 1.0f);
    p = fmaf(p, f, 1.0f);
    float s = __int_as_float((e + 127) << 23);
    return p * s;
}

__device__ __forceinline__ float fast_sigmoid(float x) {
    return 1.0f / (1.0f + fast_exp(-x));
}

__device__ __forceinline__ float fast_softplus(float x) {
    if (x > 20.0f) return x;
    return log1pf(fast_exp(x));
}

// ---------------------------------------------------------------------------
// Sinusoidal positional encoding: pe[n, 2i]=sin(n*div_i), pe[n,2i+1]=cos
// ---------------------------------------------------------------------------
__global__ void pe_kernel() {
    int n = blockIdx.x;
    int i = threadIdx.x;  // 0..127
    float div = expf((float)(2 * i) * (-0.03597867333f));  // -ln(10000)/256
    float ang = (float)n * div;
    g_pe[n * PDIM + 2 * i]     = sinf(ang);
    g_pe[n * PDIM + 2 * i + 1] = cosf(ang);
}

// ---------------------------------------------------------------------------
// Generic 128x128x8 register-blocked SGEMM: C = A[M,K] * B[K,N] (+ bias[N])
// M % 128 == 0, N % 128 == 0, K % 8 == 0 (all our shapes satisfy this)
// ---------------------------------------------------------------------------
__global__ void __launch_bounds__(256) sgemm_nn(
    const float* __restrict__ A, const float* __restrict__ B,
    const float* __restrict__ bias, float* __restrict__ C,
    int M, int Nc, int K)
{
    __shared__ float As[8][128];
    __shared__ float Bs[8][128];
    int tid = threadIdx.x;
    int bx = blockIdx.x, by = blockIdx.y;
    int tx = tid & 15, ty = tid >> 4;
    int arow = tid >> 1, acol = (tid & 1) * 4;
    int brow = tid >> 5, bcol = (tid & 31) * 4;
    const float* Ab = A + (size_t)by * 128 * K;
    const float* Bb = B + (size_t)bx * 128;
    float acc[8][8] = {};
    for (int k0 = 0; k0 < K; k0 += 8) {
        float4 av = *(const float4*)(Ab + (size_t)arow * K + k0 + acol);
        As[acol + 0][arow] = av.x; As[acol + 1][arow] = av.y;
        As[acol + 2][arow] = av.z; As[acol + 3][arow] = av.w;
        *(float4*)&Bs[brow][bcol] =
            *(const float4*)(Bb + (size_t)(k0 + brow) * Nc + bcol);
        __syncthreads();
#pragma unroll
        for (int kk = 0; kk < 8; kk++) {
            float4 a0 = *(float4*)&As[kk][ty * 8];
            float4 a1 = *(float4*)&As[kk][ty * 8 + 4];
            float4 b0 = *(float4*)&Bs[kk][tx * 8];
            float4 b1 = *(float4*)&Bs[kk][tx * 8 + 4];
            float ar[8] = {a0.x, a0.y, a0.z, a0.w, a1.x, a1.y, a1.z, a1.w};
            float br[8] = {b0.x, b0.y, b0.z, b0.w, b1.x, b1.y, b1.z, b1.w};
#pragma unroll
            for (int i = 0; i < 8; i++)
#pragma unroll
                for (int j = 0; j < 8; j++)
                    acc[i][j] = fmaf(ar[i], br[j], acc[i][j]);
        }
        __syncthreads();
    }
#pragma unroll
    for (int i = 0; i < 8; i++) {
        int r = by * 128 + ty * 8 + i;
#pragma unroll
        for (int j = 0; j < 8; j += 4) {
            int c = bx * 128 + tx * 8 + j;
            float4 v;
            v.x = acc[i][j]; v.y = acc[i][j + 1];
            v.z = acc[i][j + 2]; v.w = acc[i][j + 3];
            if (bias) {
                v.x += bias[c]; v.y += bias[c + 1];
                v.z += bias[c + 2]; v.w += bias[c + 3];
            }
            *(float4*)(C + (size_t)r * Nc + c) = v;
        }
    }
}

// ---------------------------------------------------------------------------
// Score GEMM: per-t C = Q[t] * K[t]^T / 16 + gate_bias; fused sigmoid.
// Writes logits & probs. Q,K: [T, N, H] row-major.
// ---------------------------------------------------------------------------
__global__ void __launch_bounds__(256) score_kernel(
    const float* __restrict__ Q, const float* __restrict__ Kk,
    const float* __restrict__ gb_ptr,
    float* __restrict__ probs, float* __restrict__ logits)
{
    int t = blockIdx.z;
    const float* A = Q  + (size_t)t * NNODE * HDIM;
    const float* B = Kk + (size_t)t * NNODE * HDIM;
    __shared__ float As[8][128];
    __shared__ float Bs[8][128];
    int tid = threadIdx.x;
    int bx = blockIdx.x, by = blockIdx.y;
    int tx = tid & 15, ty = tid >> 4;
    int lrow = tid >> 1, lcol = (tid & 1) * 4;
    float acc[8][8] = {};
    for (int k0 = 0; k0 < HDIM; k0 += 8) {
        float4 av = *(const float4*)(A + (size_t)(by * 128 + lrow) * HDIM + k0 + lcol);
        float4 bv = *(const float4*)(B + (size_t)(bx * 128 + lrow) * HDIM + k0 + lcol);
        As[lcol + 0][lrow] = av.x; As[lcol + 1][lrow] = av.y;
        As[lcol + 2][lrow] = av.z; As[lcol + 3][lrow] = av.w;
        Bs[lcol + 0][lrow] = bv.x; Bs[lcol + 1][lrow] = bv.y;
        Bs[lcol + 2][lrow] = bv.z; Bs[lcol + 3][lrow] = bv.w;
        __syncthreads();
#pragma unroll
        for (int kk = 0; kk < 8; kk++) {
            float4 a0 = *(float4*)&As[kk][ty * 8];
            float4 a1 = *(float4*)&As[kk][ty * 8 + 4];
            float4 b0 = *(float4*)&Bs[kk][tx * 8];
            float4 b1 = *(float4*)&Bs[kk][tx * 8 + 4];
            float ar[8] = {a0.x, a0.y, a0.z, a0.w, a1.x, a1.y, a1.z, a1.w};
            float br[8] = {b0.x, b0.y, b0.z, b0.w, b1.x, b1.y, b1.z, b1.w};
#pragma unroll
            for (int i = 0; i < 8; i++)
#pragma unroll
                for (int j = 0; j < 8; j++)
                    acc[i][j] = fmaf(ar[i], br[j], acc[i][j]);
        }
        __syncthreads();
    }
    float gb = *gb_ptr;
#pragma unroll
    for (int i = 0; i < 8; i++) {
        int r = by * 128 + ty * 8 + i;
        size_t base = ((size_t)t * NNODE + r) * NNODE;
#pragma unroll
        for (int j = 0; j < 8; j++) {
            int c = bx * 128 + tx * 8 + j;
            float lg = acc[i][j] * 0.0625f + gb;
            logits[base + c] = lg;
            probs[base + c]  = fast_sigmoid(lg);
        }
    }
}

// ---------------------------------------------------------------------------
// Sparse aggregation: out[t,i,:] = sum_j adj[t,i,j] * m[(t,)j,:]
// adj entries are exactly 0.0 / 1.0 (2% dense) -> compact nonzero list.
// ---------------------------------------------------------------------------
__global__ void agg_kernel(const float* __restrict__ adj,
                           const float* __restrict__ m,
                           float* __restrict__ out, int per_t)
{
    int i = blockIdx.x, t = blockIdx.y;
    const float* arow = adj + ((size_t)t * NNODE + i) * NNODE;
    __shared__ int s_idx[NNODE];
    __shared__ int s_cnt;
    if (threadIdx.x == 0) s_cnt = 0;
    __syncthreads();
    for (int j = threadIdx.x; j < NNODE; j += 256) {
        if (arow[j] != 0.0f) {
            int p = atomicAdd(&s_cnt, 1);
            s_idx[p] = j;
        }
    }
    __syncthreads();
    int cnt = s_cnt;
    int h = threadIdx.x;
    const float* mb = m + (per_t ? (size_t)t * NNODE * HDIM : 0);
    float acc = 0.0f;
    for (int p = 0; p < cnt; p++)
        acc += mb[(size_t)s_idx[p] * HDIM + h];
    out[((size_t)t * NNODE + i) * HDIM + h] = acc;
}

// ---------------------------------------------------------------------------
// Concat into [NT, 512]: first half is pe[n] (layer1) or x[r] (layer2),
// second half is agg[r]. Rows are t-major: r = t*N + n.
// ---------------------------------------------------------------------------
__global__ void concat_kernel(const float* __restrict__ first,
                              const float* __restrict__ agg,
                              float* __restrict__ dst, int bcast_pe)
{
    size_t id = (size_t)blockIdx.x * 256 + threadIdx.x;  // NT*512 elems
    int r = (int)(id >> 9);
    int c = (int)(id & 511);
    float v;
    if (c < 256)
        v = bcast_pe ? g_pe[(size_t)(r & 1023) * PDIM + c]
                     : first[(size_t)r * HDIM + c];
    else
        v = agg[(size_t)r * HDIM + (c - 256)];
    dst[id] = v;
}

// ---------------------------------------------------------------------------
// ReLU (optional) + LayerNorm over 256-wide rows, in-place capable.
// ---------------------------------------------------------------------------
__global__ void relu_ln_kernel(const float* __restrict__ in,
                               const float* __restrict__ gam,
                               const float* __restrict__ bet,
                               float* __restrict__ out, int do_relu)
{
    int row = blockIdx.x, tid = threadIdx.x;
    float v = in[(size_t)row * HDIM + tid];
    if (do_relu) v = fmaxf(v, 0.0f);
    float s = v, q = v * v;
#pragma unroll
    for (int o = 16; o > 0; o >>= 1) {
        s += __shfl_xor_sync(0xffffffffu, s, o);
        q += __shfl_xor_sync(0xffffffffu, q, o);
    }
    __shared__ float ss[8], qq[8];
    __shared__ float s_mu, s_rstd;
    int w = tid >> 5;
    if ((tid & 31) == 0) { ss[w] = s; qq[w] = q; }
    __syncthreads();
    if (tid == 0) {
        float S = 0, QQ = 0;
        for (int i = 0; i < 8; i++) { S += ss[i]; QQ += qq[i]; }
        float mu = S * (1.0f / 256.0f);
        float var = QQ * (1.0f / 256.0f) - mu * mu;
        s_mu = mu; s_rstd = rsqrtf(var + 1e-5f);
    }
    __syncthreads();
    out[(size_t)row * HDIM + tid] = (v - s_mu) * s_rstd * gam[tid] + bet[tid];
}

// LN of x2 rows (t-major) written to xn rows (n-major): mamba pre-norm + transpose
__global__ void ln_seq_kernel(const float* __restrict__ gam,
                              const float* __restrict__ bet)
{
    int rin = blockIdx.x;              // t*N + n
    int tid = threadIdx.x;
    int t = rin >> 10, n = rin & 1023;
    float v = g_x2[(size_t)rin * HDIM + tid];
    float s = v, q = v * v;
#pragma unroll
    for (int o = 16; o > 0; o >>= 1) {
        s += __shfl_xor_sync(0xffffffffu, s, o);
        q += __shfl_xor_sync(0xffffffffu, q, o);
    }
    __shared__ float ss[8], qq[8];
    __shared__ float s_mu, s_rstd;
    int w = tid >> 5;
    if ((tid & 31) == 0) { ss[w] = s; qq[w] = q; }
    __syncthreads();
    if (tid == 0) {
        float S = 0, QQ = 0;
        for (int i = 0; i < 8; i++) { S += ss[i]; QQ += qq[i]; }
        float mu = S * (1.0f / 256.0f);
        float var = QQ * (1.0f / 256.0f) - mu * mu;
        s_mu = mu; s_rstd = rsqrtf(var + 1e-5f);
    }
    __syncthreads();
    g_xn[((size_t)n * TSTEP + t) * HDIM + tid] =
        (v - s_mu) * s_rstd * gam[tid] + bet[tid];
}

// silu on first half of xp -> x1
__global__ void silu_kernel() {
    size_t id = (size_t)blockIdx.x * 256 + threadIdx.x;  // NT*512
    size_t r = id >> 9, e = id & 511;
    float v = g_xp[r * 1024 + e];
    g_x1[id] = v * fast_sigmoid(v);
}

// Transpose [512,16] weights to [16,512] for vectorized small-N projections
__global__ void transpose_w3(const float* __restrict__ dw,
                             const float* __restrict__ bw,
                             const float* __restrict__ cw)
{
    int id = blockIdx.x * 256 + threadIdx.x;  // 8192
    if (id < EDIM * DTR) {
        int k = id >> 4, n = id & 15;
        g_dwT[n * EDIM + k] = dw[id];
        g_bwT[n * EDIM + k] = bw[id];
        g_cwT[n * EDIM + k] = cw[id];
    }
}

// d1 = x1@delta_w + delta_b; Bm = x1@Bp_w + Bp_b; Cm = x1@Cp_w + Cp_b  (N=16 each)
__global__ void proj3_kernel(const float* __restrict__ db,
                             const float* __restrict__ bb,
                             const float* __restrict__ cb)
{
    int r = blockIdx.x * 16 + (threadIdx.x >> 4);
    int n = threadIdx.x & 15;
    const float4* a4 = (const float4*)(g_x1 + (size_t)r * EDIM);
    const float4* d4 = (const float4*)(g_dwT + n * EDIM);
    const float4* b4 = (const float4*)(g_bwT + n * EDIM);
    const float4* c4 = (const float4*)(g_cwT + n * EDIM);
    float ad = 0, ab = 0, ac = 0;
#pragma unroll 4
    for (int k = 0; k < EDIM / 4; k++) {
        float4 a = a4[k];
        float4 d = d4[k], b = b4[k], c = c4[k];
        ad = fmaf(a.x, d.x, fmaf(a.y, d.y, fmaf(a.z, d.z, fmaf(a.w, d.w, ad))));
        ab = fmaf(a.x, b.x, fmaf(a.y, b.y, fmaf(a.z, b.z, fmaf(a.w, b.w, ab))));
        ac = fmaf(a.x, c.x, fmaf(a.y, c.y, fmaf(a.z, c.z, fmaf(a.w, c.w, ac))));
    }
    size_t o = (size_t)r * 16 + n;
    g_d1[o] = ad + db[n];
    g_Bm[o] = ab + bb[n];
    g_Cm[o] = ac + cb[n];
}

// delta = softplus(d1 @ dt_w + dt_b)   (K=16)
__global__ void dtsp_kernel(const float* __restrict__ dtw,
                            const float* __restrict__ dtb)
{
    size_t id = (size_t)blockIdx.x * 256 + threadIdx.x;  // NT*512
    size_t r = id >> 9;
    int e = (int)(id & 511);
    const float* d1r = g_d1 + r * 16;
    float acc = dtb[e];
#pragma unroll
    for (int k = 0; k < 16; k++)
        acc = fmaf(d1r[k], dtw[k * EDIM + e], acc);
    g_delta[id] = fast_softplus(acc);
}

// ---------------------------------------------------------------------------
// Selective scan over T=32. One block per node n, thread per channel e.
// h[SD] kept in registers. Writes y (already includes D skip + gate silu).
// ---------------------------------------------------------------------------
__global__ void __launch_bounds__(512) scan_kernel(
    const float* __restrict__ A_log, const float* __restrict__ D_vec)
{
    int n = blockIdx.x;
    int e = threadIdx.x;  // 0..511
    float A[SDIM], h[SDIM];
#pragma unroll
    for (int s = 0; s < SDIM; s++) {
        A[s] = -fast_exp(A_log[e * SDIM + s]);
        h[s] = 0.0f;
    }
    float Dv = D_vec[e];
    __shared__ float sb[SDIM], sc[SDIM];
    for (int t = 0; t < TSTEP; t++) {
        size_t r = (size_t)n * TSTEP + t;
        if (e < 16)       sb[e]      = g_Bm[r * 16 + e];
        else if (e < 32)  sc[e - 16] = g_Cm[r * 16 + (e - 16)];
        __syncthreads();
        float dt = g_delta[r * EDIM + e];
        float xt = g_x1[r * EDIM + e];
        float dx = dt * xt;
        float yv = 0.0f;
#pragma unroll
        for (int s = 0; s < SDIM; s++) {
            h[s] = fmaf(fast_exp(dt * A[s]), h[s], dx * sb[s]);
            yv  = fmaf(sc[s], h[s], yv);
        }
        yv += xt * Dv;
        float g = g_xp[r * 1024 + EDIM + e];
        yv *= g * fast_sigmoid(g);
        g_y[r * EDIM + e] = yv;
        __syncthreads();
    }
}

// outs[t*N+n, h] = mb[n*T+t, h] + x2[t*N+n, h]   (residual + transpose back)
__global__ void write_outs_kernel(float* __restrict__ outs) {
    int ro = blockIdx.x;               // t*N + n
    int tid = threadIdx.x;
    int t = ro >> 10, n = ro & 1023;
    size_t src = ((size_t)n * TSTEP + t) * HDIM + tid;
    size_t dst = (size_t)ro * HDIM + tid;
    outs[dst] = g_mb[src] + g_x2[dst];
}

// ---------------------------------------------------------------------------
// Host launch
// ---------------------------------------------------------------------------
extern "C" void kernel_launch(void* const* d_in, const int* in_sizes, int n_in,
                              void* d_out, int out_size)
{
    const float* adj     = (const float*)d_in[0];
    const float* msg1_w  = (const float*)d_in[1];
    const float* msg1_b  = (const float*)d_in[2];
    const float* upd1_w  = (const float*)d_in[3];
    const float* upd1_b  = (const float*)d_in[4];
    const float* ln1_g   = (const float*)d_in[5];
    const float* ln1_b   = (const float*)d_in[6];
    const float* msg2_w  = (const float*)d_in[7];
    const float* msg2_b  = (const float*)d_in[8];
    const float* upd2_w  = (const float*)d_in[9];
    const float* upd2_b  = (const float*)d_in[10];
    const float* ln2_g   = (const float*)d_in[11];
    const float* ln2_b   = (const float*)d_in[12];
    const float* mbln_g  = (const float*)d_in[13];
    const float* mbln_b  = (const float*)d_in[14];
    const float* in_w    = (const float*)d_in[15];
    const float* in_b    = (const float*)d_in[16];
    const float* delta_w = (const float*)d_in[17];
    const float* delta_b = (const float*)d_in[18];
    const float* dt_w    = (const float*)d_in[19];
    const float* dt_b    = (const float*)d_in[20];
    const float* Bp_w    = (const float*)d_in[21];
    const float* Bp_b    = (const float*)d_in[22];
    const float* Cp_w    = (const float*)d_in[23];
    const float* Cp_b    = (const float*)d_in[24];
    const float* A_log   = (const float*)d_in[25];
    const float* D_vec   = (const float*)d_in[26];
    const float* out_w   = (const float*)d_in[27];
    const float* out_b   = (const float*)d_in[28];
    const float* q_w     = (const float*)d_in[29];
    const float* k_w     = (const float*)d_in[30];
    const float* gate_b  = (const float*)d_in[31];

    float* out    = (float*)d_out;
    float* outs   = out;                                    // [T,N,H]
    float* probs  = out + (size_t)TSTEP * NNODE * HDIM;     // [T,N,N]
    float* logits = probs + (size_t)TSTEP * NNODE * NNODE;  // [T,N,N]

    float *pe_, *m1_, *cbuf_, *x_, *agg_, *m2_, *x2_, *xn_, *xp_, *y_, *mb_, *q_, *k_;
    cudaGetSymbolAddress((void**)&pe_,   g_pe);
    cudaGetSymbolAddress((void**)&m1_,   g_m1);
    cudaGetSymbolAddress((void**)&cbuf_, g_cbuf);
    cudaGetSymbolAddress((void**)&x_,    g_x);
    cudaGetSymbolAddress((void**)&agg_,  g_agg);
    cudaGetSymbolAddress((void**)&m2_,   g_m2);
    cudaGetSymbolAddress((void**)&x2_,   g_x2);
    cudaGetSymbolAddress((void**)&xn_,   g_xn);
    cudaGetSymbolAddress((void**)&xp_,   g_xp);
    cudaGetSymbolAddress((void**)&y_,    g_y);
    cudaGetSymbolAddress((void**)&mb_,   g_mb);
    cudaGetSymbolAddress((void**)&q_,    g_q);
    cudaGetSymbolAddress((void**)&k_,    g_k);

    // 1. positional encoding + m1 = pe @ msg1_w + b
    pe_kernel<<<NNODE, 128>>>();
    sgemm_nn<<<dim3(HDIM / 128, NNODE / 128), 256>>>(pe_, msg1_w, msg1_b, m1_,
                                                     NNODE, HDIM, PDIM);
    // 2. agg1 (sparse), concat(pe, agg1), upd1 GEMM, relu+LN -> g_x
    agg_kernel<<<dim3(NNODE, TSTEP), 256>>>(adj, m1_, agg_, 0);
    concat_kernel<<<(NT * 512) / 256, 256>>>(nullptr, agg_, cbuf_, 1);
    sgemm_nn<<<dim3(HDIM / 128, NT / 128), 256>>>(cbuf_, upd1_w, upd1_b, x_,
                                                  NT, HDIM, 512);
    relu_ln_kernel<<<NT, 256>>>(x_, ln1_g, ln1_b, x_, 1);
    // 3. m2 GEMM, agg2, concat(x, agg2), upd2 GEMM, relu+LN -> g_x2
    sgemm_nn<<<dim3(HDIM / 128, NT / 128), 256>>>(x_, msg2_w, msg2_b, m2_,
                                                  NT, HDIM, HDIM);
    agg_kernel<<<dim3(NNODE, TSTEP), 256>>>(adj, m2_, agg_, 1);
    concat_kernel<<<(NT * 512) / 256, 256>>>(x_, agg_, cbuf_, 0);
    sgemm_nn<<<dim3(HDIM / 128, NT / 128), 256>>>(cbuf_, upd2_w, upd2_b, x2_,
                                                  NT, HDIM, 512);
    relu_ln_kernel<<<NT, 256>>>(x2_, ln2_g, ln2_b, x2_, 1);
    // 4. Mamba: LN+transpose -> xn; in_proj -> xp; silu(x1)
    ln_seq_kernel<<<NT, 256>>>(mbln_g, mbln_b);
    sgemm_nn<<<dim3(1024 / 128, NT / 128), 256>>>(xn_, in_w, in_b, xp_,
                                                  NT, 1024, HDIM);
    silu_kernel<<<(NT * EDIM) / 256, 256>>>();
    // 5. small projections (delta pre, B, C) + dt proj + softplus
    transpose_w3<<<(EDIM * DTR + 255) / 256, 256>>>(delta_w, Bp_w, Cp_w);
    proj3_kernel<<<NT / 16, 256>>>(delta_b, Bp_b, Cp_b);
    dtsp_kernel<<<(NT * EDIM) / 256, 256>>>(dt_w, dt_b);
    // 6. selective scan (fused D skip + gate silu) -> g_y
    scan_kernel<<<NNODE, EDIM>>>(A_log, D_vec);
    // 7. out projection + residual -> outs (t-major, into d_out)
    sgemm_nn<<<dim3(HDIM / 128, NT / 128), 256>>>(y_, out_w, out_b, mb_,
                                                  NT, HDIM, EDIM);
    write_outs_kernel<<<NT, 256>>>(outs);
    // 8. q/k projections + fused score/sigmoid head
    sgemm_nn<<<dim3(HDIM / 128, NT / 128), 256>>>(outs, q_w, nullptr, q_,
                                                  NT, HDIM, HDIM);
    sgemm_nn<<<dim3(HDIM / 128, NT / 128), 256>>>(outs, k_w, nullptr, k_,
                                                  NT, HDIM, HDIM);
    score_kernel<<<dim3(NNODE / 128, NNODE / 128, TSTEP), 256>>>(
        q_, k_, gate_b, probs, logits);
}

// round 5
// speedup vs baseline: 1.5562x; 1.5562x over previous
#include <cuda_runtime.h>
#include <cuda_bf16.h>
#include <cstdint>

// Problem constants
#define NNODE 1024
#define TSTEP 32
#define HDIM  256
#define PDIM  256
#define EDIM  512
#define DTR   16
#define SDIM  16
#define NT    (NNODE * TSTEP)   // 32768

#define SMEM_SWIZZLE_128B(byte_offset) \
    ((byte_offset) ^ (((byte_offset) >> 3) & 0x70))

// ===========================================================================
// Scratch (device globals)
// ===========================================================================
__device__ float g_pe   [NNODE * PDIM];
__device__ float g_m1   [NNODE * HDIM];
__device__ float g_x    [(size_t)NT * HDIM];
__device__ float g_agg  [(size_t)NT * HDIM];
__device__ float g_m2   [(size_t)NT * HDIM];
__device__ float g_x2   [(size_t)NT * HDIM];
__device__ float g_xp   [(size_t)NT * 1024];
__device__ float g_x1   [(size_t)NT * EDIM];
__device__ float g_delta[(size_t)NT * EDIM];
__device__ float g_d1   [(size_t)NT * DTR];
__device__ float g_Bm   [(size_t)NT * SDIM];
__device__ float g_Cm   [(size_t)NT * SDIM];
__device__ float g_mb   [(size_t)NT * HDIM];
__device__ float g_dwT  [DTR * EDIM];
__device__ float g_bwT  [DTR * EDIM];
__device__ float g_cwT  [DTR * EDIM];
// bf16 hi/lo split buffers
__device__ __nv_bfloat16 g_c1h[(size_t)NT * 512];
__device__ __nv_bfloat16 g_c1l[(size_t)NT * 512];
__device__ __nv_bfloat16 g_xh [(size_t)NT * HDIM];
__device__ __nv_bfloat16 g_xl [(size_t)NT * HDIM];
__device__ __nv_bfloat16 g_qh [(size_t)NT * HDIM];
__device__ __nv_bfloat16 g_ql [(size_t)NT * HDIM];
__device__ __nv_bfloat16 g_kh [(size_t)NT * HDIM];
__device__ __nv_bfloat16 g_kl [(size_t)NT * HDIM];
__device__ __nv_bfloat16 g_wh [1024 * 512];
__device__ __nv_bfloat16 g_wl [1024 * 512];

__device__ __forceinline__ void bsplit(float v, __nv_bfloat16& h, __nv_bfloat16& l) {
    h = __float2bfloat16(v);
    l = __float2bfloat16(v - __bfloat162float(h));
}

// ===========================================================================
// Fast math (FMA-pipe exp)
// ===========================================================================
__device__ __forceinline__ float fast_exp(float x) {
    x = fminf(fmaxf(x, -87.0f), 87.0f);
    float y = x * 1.44269504088896340736f;
    float t = y + 12582912.0f;
    int   e = __float_as_int(t) - 0x4B400000;
    float r = t - 12582912.0f;
    float f = (y - r) * 0.69314718055994530942f;
    float p = 1.3888889e-3f;
    p = fmaf(p, f, 8.3333333e-3f);
    p = fmaf(p, f, 4.1666668e-2f);
    p = fmaf(p, f, 1.6666667e-1f);
    p = fmaf(p, f, 0.5f);
    p = fmaf(p, f, 1.0f);
    p = fmaf(p, f, 1.0f);
    float s = __int_as_float((e + 127) << 23);
    return p * s;
}
__device__ __forceinline__ float fast_sigmoid(float x) {
    return 1.0f / (1.0f + fast_exp(-x));
}
__device__ __forceinline__ float fast_softplus(float x) {
    if (x > 20.0f) return x;
    return log1pf(fast_exp(x));
}

// ===========================================================================
// Warp MMA / async-copy primitives (all baseline sm_80+ — no 'a' features)
// ===========================================================================
__device__ __forceinline__ uint32_t smem_u32(const void* p) {
    uint32_t a;
    asm("{ .reg .u64 t; cvta.to.shared.u64 t, %1; cvt.u32.u64 %0, t; }"
        : "=r"(a) : "l"(p));
    return a;
}
__device__ __forceinline__ void ldsm_x4(uint32_t* r, uint32_t addr) {
    asm volatile("ldmatrix.sync.aligned.m8n8.x4.shared.b16 {%0,%1,%2,%3}, [%4];"
        : "=r"(r[0]), "=r"(r[1]), "=r"(r[2]), "=r"(r[3]) : "r"(addr));
}
__device__ __forceinline__ void mma16816(float* c, const uint32_t* a,
                                         uint32_t b0, uint32_t b1) {
    asm volatile(
        "mma.sync.aligned.m16n8k16.row.col.f32.bf16.bf16.f32 "
        "{%0,%1,%2,%3}, {%4,%5,%6,%7}, {%8,%9}, {%0,%1,%2,%3};"
        : "+f"(c[0]), "+f"(c[1]), "+f"(c[2]), "+f"(c[3])
        : "r"(a[0]), "r"(a[1]), "r"(a[2]), "r"(a[3]), "r"(b0), "r"(b1));
}
__device__ __forceinline__ void cp_async16(uint32_t saddr, const void* gaddr) {
    asm volatile("cp.async.cg.shared.global [%0], [%1], 16;"
        :: "r"(saddr), "l"(gaddr));
}
#define CP_COMMIT()  asm volatile("cp.async.commit_group;" ::: "memory")
#define CP_WAIT(n)   asm volatile("cp.async.wait_group %0;" :: "n"(n) : "memory")

// ===========================================================================
// HMMA 3xBF16 GEMM: C[M,Nc] = A[M,K] @ B[Nc,K]^T  (A,B hi/lo split, fp32 acc)
// 128x128 CTA tile, 8 warps (2M x 4N), warp tile 64x32, K-chunks of 64,
// 2-stage cp.async pipeline, SW128-swizzled smem.
// mode 0: fp32 out (+bias); mode 1: score head (probs+logits);
// mode 2: bf16 hi/lo split output.
// ===========================================================================
__global__ void __launch_bounds__(256, 2) gemm3x(
    const __nv_bfloat16* __restrict__ Ah, const __nv_bfloat16* __restrict__ Al,
    const __nv_bfloat16* __restrict__ Bh, const __nv_bfloat16* __restrict__ Bl,
    const float* __restrict__ bias,
    void* __restrict__ out1, void* __restrict__ out2,
    const float* __restrict__ gb_ptr,
    int K, int Nc, int mode,
    size_t aBatch, size_t bBatch, size_t cBatch)
{
    extern __shared__ __align__(16) char smem[];
    const uint32_t sb = smem_u32(smem);
    const int tid = threadIdx.x;
    const int wid = tid >> 5, lane = tid & 31;
    const int wm = wid & 1, wn = wid >> 1;

    const size_t zA = (size_t)blockIdx.z * aBatch;
    const size_t zB = (size_t)blockIdx.z * bBatch;
    const __nv_bfloat16* Aseg[3] = { Ah + zA, Ah + zA, Al + zA };
    const __nv_bfloat16* Bseg[3] = { Bh + zB, Bl + zB, Bh + zB };

    const int m0 = blockIdx.y * 128, n0 = blockIdx.x * 128;
    const int ksub = K >> 6;           // 64-wide chunks per segment
    const int nk = 3 * ksub;

    // cp.async mapping: 1024 16B-chunks per 16KB tile, 4 per thread
    const int lrow = tid >> 1;                 // unused helper removed
    (void)lrow;

    float acc[4][4][4];
#pragma unroll
    for (int i = 0; i < 4; i++)
#pragma unroll
        for (int j = 0; j < 4; j++)
#pragma unroll
            for (int r = 0; r < 4; r++) acc[i][j][r] = 0.0f;

    // precomputed ldmatrix lane offsets (within-tile byte offsets)
    const int a_r = ((lane >> 3) & 1) * 8 + (lane & 7);
    const int a_c = ((lane >> 4) & 1) * 8;
    const int b_n = ((lane >> 4) & 1) * 8 + (lane & 7);
    const int b_k = ((lane >> 3) & 1) * 8;

    auto load_tile = [&](const __nv_bfloat16* g, int row0, int k0, uint32_t sdst) {
#pragma unroll
        for (int j = 0; j < 4; j++) {
            int c = tid + j * 256;          // 0..1023
            int row = c >> 3, ch = c & 7;
            const void* gp = g + (size_t)(row0 + row) * K + k0 + ch * 8;
            uint32_t sp = sdst + SMEM_SWIZZLE_128B((uint32_t)(row * 128 + ch * 16));
            cp_async16(sp, gp);
        }
    };

    // prologue: chunk 0 -> buffer 0
    load_tile(Aseg[0], m0, 0, sb);
    load_tile(Bseg[0], n0, 0, sb + 16384);
    CP_COMMIT();

    for (int i = 0; i < nk; i++) {
        int b = i & 1;
        if (i + 1 < nk) {
            int seg = (i + 1) / ksub;
            int k0 = ((i + 1) - seg * ksub) << 6;
            uint32_t sd = sb + (uint32_t)(b ^ 1) * 32768u;
            load_tile(Aseg[seg], m0, k0, sd);
            load_tile(Bseg[seg], n0, k0, sd + 16384);
            CP_COMMIT();
            CP_WAIT(1);
        } else {
            CP_COMMIT();
            CP_WAIT(0);
        }
        __syncthreads();

        uint32_t abase = sb + (uint32_t)b * 32768u;
        uint32_t bbase = abase + 16384u;
#pragma unroll
        for (int ks = 0; ks < 4; ks++) {
            uint32_t afr[4][4];
#pragma unroll
            for (int mi = 0; mi < 4; mi++) {
                int row = wm * 64 + mi * 16 + a_r;
                int col = ks * 16 + a_c;
                ldsm_x4(afr[mi],
                        abase + SMEM_SWIZZLE_128B((uint32_t)(row * 128 + col * 2)));
            }
            uint32_t bfr[2][4];
#pragma unroll
            for (int j = 0; j < 2; j++) {
                int n = wn * 32 + j * 16 + b_n;
                int kc = ks * 16 + b_k;
                ldsm_x4(bfr[j],
                        bbase + SMEM_SWIZZLE_128B((uint32_t)(n * 128 + kc * 2)));
            }
#pragma unroll
            for (int mi = 0; mi < 4; mi++)
#pragma unroll
                for (int ni = 0; ni < 4; ni++) {
                    const uint32_t* bs = bfr[ni >> 1];
                    mma16816(acc[mi][ni], afr[mi],
                             bs[(ni & 1) * 2], bs[(ni & 1) * 2 + 1]);
                }
        }
        __syncthreads();
    }

    // ---------------- epilogue ----------------
    const int rg = lane >> 2;            // 0..7
    const int cg = (lane & 3) * 2;       // 0,2,4,6
#pragma unroll
    for (int mi = 0; mi < 4; mi++) {
#pragma unroll
        for (int ni = 0; ni < 4; ni++) {
            float* c = acc[mi][ni];
            int gr0 = m0 + wm * 64 + mi * 16 + rg;
            int gc  = n0 + wn * 32 + ni * 8 + cg;
            if (mode == 0) {
                float* C = (float*)out1;
                float b0 = bias ? bias[gc] : 0.0f;
                float b1 = bias ? bias[gc + 1] : 0.0f;
                *(float2*)(C + (size_t)gr0 * Nc + gc)       = {c[0] + b0, c[1] + b1};
                *(float2*)(C + (size_t)(gr0 + 8) * Nc + gc) = {c[2] + b0, c[3] + b1};
            } else if (mode == 1) {
                float gb = *gb_ptr;
                float* P = (float*)out1 + (size_t)blockIdx.z * cBatch;
                float* L = (float*)out2 + (size_t)blockIdx.z * cBatch;
                float l0 = c[0] * 0.0625f + gb, l1 = c[1] * 0.0625f + gb;
                float l2 = c[2] * 0.0625f + gb, l3 = c[3] * 0.0625f + gb;
                *(float2*)(L + (size_t)gr0 * Nc + gc)       = {l0, l1};
                *(float2*)(L + (size_t)(gr0 + 8) * Nc + gc) = {l2, l3};
                *(float2*)(P + (size_t)gr0 * Nc + gc)       =
                    {fast_sigmoid(l0), fast_sigmoid(l1)};
                *(float2*)(P + (size_t)(gr0 + 8) * Nc + gc) =
                    {fast_sigmoid(l2), fast_sigmoid(l3)};
            } else {  // mode 2: bf16 hi/lo split
                __nv_bfloat16* H  = (__nv_bfloat16*)out1;
                __nv_bfloat16* Lo = (__nv_bfloat16*)out2;
                __nv_bfloat16 h0, l0, h1, l1;
                bsplit(c[0], h0, l0); bsplit(c[1], h1, l1);
                *(__nv_bfloat162*)(H  + (size_t)gr0 * Nc + gc) = {h0, h1};
                *(__nv_bfloat162*)(Lo + (size_t)gr0 * Nc + gc) = {l0, l1};
                bsplit(c[2], h0, l0); bsplit(c[3], h1, l1);
                *(__nv_bfloat162*)(H  + (size_t)(gr0 + 8) * Nc + gc) = {h0, h1};
                *(__nv_bfloat162*)(Lo + (size_t)(gr0 + 8) * Nc + gc) = {l0, l1};
            }
        }
    }
}

// ===========================================================================
// Small SIMT SGEMM (tiny m1 = pe @ msg1_w only)
// ===========================================================================
__global__ void __launch_bounds__(256) sgemm_nn(
    const float* __restrict__ A, const float* __restrict__ B,
    const float* __restrict__ bias, float* __restrict__ C,
    int M, int Nc, int K)
{
    __shared__ float As[8][128];
    __shared__ float Bs[8][128];
    int tid = threadIdx.x;
    int bx = blockIdx.x, by = blockIdx.y;
    int tx = tid & 15, ty = tid >> 4;
    int arow = tid >> 1, acol = (tid & 1) * 4;
    int brow = tid >> 5, bcol = (tid & 31) * 4;
    const float* Ab = A + (size_t)by * 128 * K;
    const float* Bb = B + (size_t)bx * 128;
    float acc[8][8] = {};
    for (int k0 = 0; k0 < K; k0 += 8) {
        float4 av = *(const float4*)(Ab + (size_t)arow * K + k0 + acol);
        As[acol + 0][arow] = av.x; As[acol + 1][arow] = av.y;
        As[acol + 2][arow] = av.z; As[acol + 3][arow] = av.w;
        *(float4*)&Bs[brow][bcol] =
            *(const float4*)(Bb + (size_t)(k0 + brow) * Nc + bcol);
        __syncthreads();
#pragma unroll
        for (int kk = 0; kk < 8; kk++) {
            float4 a0 = *(float4*)&As[kk][ty * 8];
            float4 a1 = *(float4*)&As[kk][ty * 8 + 4];
            float4 b0 = *(float4*)&Bs[kk][tx * 8];
            float4 b1 = *(float4*)&Bs[kk][tx * 8 + 4];
            float ar[8] = {a0.x, a0.y, a0.z, a0.w, a1.x, a1.y, a1.z, a1.w};
            float br[8] = {b0.x, b0.y, b0.z, b0.w, b1.x, b1.y, b1.z, b1.w};
#pragma unroll
            for (int i = 0; i < 8; i++)
#pragma unroll
                for (int j = 0; j < 8; j++)
                    acc[i][j] = fmaf(ar[i], br[j], acc[i][j]);
        }
        __syncthreads();
    }
#pragma unroll
    for (int i = 0; i < 8; i++) {
        int r = by * 128 + ty * 8 + i;
#pragma unroll
        for (int j = 0; j < 8; j += 4) {
            int c = bx * 128 + tx * 8 + j;
            float4 v;
            v.x = acc[i][j] + bias[c];         v.y = acc[i][j + 1] + bias[c + 1];
            v.z = acc[i][j + 2] + bias[c + 2]; v.w = acc[i][j + 3] + bias[c + 3];
            *(float4*)(C + (size_t)r * Nc + c) = v;
        }
    }
}

// ===========================================================================
// Elementwise / helper kernels
// ===========================================================================
__global__ void pe_kernel() {
    int n = blockIdx.x;
    int i = threadIdx.x;  // 0..127
    float div = expf((float)(2 * i) * (-0.03597867333f));
    float ang = (float)n * div;
    g_pe[n * PDIM + 2 * i]     = sinf(ang);
    g_pe[n * PDIM + 2 * i + 1] = cosf(ang);
}

// weight transpose+split: W[K,N] fp32 -> g_wh/g_wl [N,K] bf16
__global__ void split_wT(const float* __restrict__ W, int K, int N) {
    int i = blockIdx.x * 256 + threadIdx.x;
    if (i < K * N) {
        int k = i / N, n = i % N;
        __nv_bfloat16 h, l; bsplit(W[i], h, l);
        g_wh[(size_t)n * K + k] = h;
        g_wl[(size_t)n * K + k] = l;
    }
}

// Sparse aggregation: out[t,i,:] = sum_j adj[t,i,j] * m[(t,)j,:]
__global__ void agg_kernel(const float* __restrict__ adj,
                           const float* __restrict__ m,
                           float* __restrict__ out, int per_t)
{
    int i = blockIdx.x, t = blockIdx.y;
    const float* arow = adj + ((size_t)t * NNODE + i) * NNODE;
    __shared__ int s_idx[NNODE];
    __shared__ int s_cnt;
    if (threadIdx.x == 0) s_cnt = 0;
    __syncthreads();
    for (int j = threadIdx.x; j < NNODE; j += 256) {
        if (arow[j] != 0.0f) {
            int p = atomicAdd(&s_cnt, 1);
            s_idx[p] = j;
        }
    }
    __syncthreads();
    int cnt = s_cnt;
    int h = threadIdx.x;
    const float* mb = m + (per_t ? (size_t)t * NNODE * HDIM : 0);
    float acc = 0.0f;
    for (int p = 0; p < cnt; p++)
        acc += mb[(size_t)s_idx[p] * HDIM + h];
    out[((size_t)t * NNODE + i) * HDIM + h] = acc;
}

// concat + bf16 split directly into g_c1h/g_c1l
__global__ void concat1_split() {
    size_t id = (size_t)blockIdx.x * 256 + threadIdx.x;  // NT*512
    int r = (int)(id >> 9), c = (int)(id & 511);
    float v = (c < 256) ? g_pe[(size_t)(r & 1023) * PDIM + c]
                        : g_agg[(size_t)r * HDIM + (c - 256)];
    __nv_bfloat16 h, l; bsplit(v, h, l);
    g_c1h[id] = h; g_c1l[id] = l;
}
__global__ void concat2_split() {
    size_t id = (size_t)blockIdx.x * 256 + threadIdx.x;
    int r = (int)(id >> 9), c = (int)(id & 511);
    float v = (c < 256) ? g_x[(size_t)r * HDIM + c]
                        : g_agg[(size_t)r * HDIM + (c - 256)];
    __nv_bfloat16 h, l; bsplit(v, h, l);
    g_c1h[id] = h; g_c1l[id] = l;
}

// ReLU + LN; optionally also writes bf16 split (for msg2 GEMM input)
__global__ void relu_ln_kernel(const float* __restrict__ in,
                               const float* __restrict__ gam,
                               const float* __restrict__ bet,
                               float* __restrict__ out, int do_split)
{
    int row = blockIdx.x, tid = threadIdx.x;
    float v = fmaxf(in[(size_t)row * HDIM + tid], 0.0f);
    float s = v, q = v * v;
#pragma unroll
    for (int o = 16; o > 0; o >>= 1) {
        s += __shfl_xor_sync(0xffffffffu, s, o);
        q += __shfl_xor_sync(0xffffffffu, q, o);
    }
    __shared__ float ss[8], qq[8];
    __shared__ float s_mu, s_rstd;
    int w = tid >> 5;
    if ((tid & 31) == 0) { ss[w] = s; qq[w] = q; }
    __syncthreads();
    if (tid == 0) {
        float S = 0, QQ = 0;
        for (int i = 0; i < 8; i++) { S += ss[i]; QQ += qq[i]; }
        float mu = S * (1.0f / 256.0f);
        float var = QQ * (1.0f / 256.0f) - mu * mu;
        s_mu = mu; s_rstd = rsqrtf(var + 1e-5f);
    }
    __syncthreads();
    float o = (v - s_mu) * s_rstd * gam[tid] + bet[tid];
    out[(size_t)row * HDIM + tid] = o;
    if (do_split) {
        __nv_bfloat16 h, l; bsplit(o, h, l);
        g_xh[(size_t)row * HDIM + tid] = h;
        g_xl[(size_t)row * HDIM + tid] = l;
    }
}

// Mamba pre-LN: read x2 (t-major), write bf16 split xn (n-major)
__global__ void ln_seq_split(const float* __restrict__ gam,
                             const float* __restrict__ bet)
{
    int rin = blockIdx.x;              // t*N + n
    int tid = threadIdx.x;
    int t = rin >> 10, n = rin & 1023;
    float v = g_x2[(size_t)rin * HDIM + tid];
    float s = v, q = v * v;
#pragma unroll
    for (int o = 16; o > 0; o >>= 1) {
        s += __shfl_xor_sync(0xffffffffu, s, o);
        q += __shfl_xor_sync(0xffffffffu, q, o);
    }
    __shared__ float ss[8], qq[8];
    __shared__ float s_mu, s_rstd;
    int w = tid >> 5;
    if ((tid & 31) == 0) { ss[w] = s; qq[w] = q; }
    __syncthreads();
    if (tid == 0) {
        float S = 0, QQ = 0;
        for (int i = 0; i < 8; i++) { S += ss[i]; QQ += qq[i]; }
        float mu = S * (1.0f / 256.0f);
        float var = QQ * (1.0f / 256.0f) - mu * mu;
        s_mu = mu; s_rstd = rsqrtf(var + 1e-5f);
    }
    __syncthreads();
    float o = (v - s_mu) * s_rstd * gam[tid] + bet[tid];
    size_t dst = ((size_t)n * TSTEP + t) * HDIM + tid;
    __nv_bfloat16 h, l; bsplit(o, h, l);
    g_xh[dst] = h; g_xl[dst] = l;
}

__global__ void silu_kernel() {
    size_t id = (size_t)blockIdx.x * 256 + threadIdx.x;  // NT*512
    size_t r = id >> 9, e = id & 511;
    float v = g_xp[r * 1024 + e];
    g_x1[id] = v * fast_sigmoid(v);
}

__global__ void transpose_w3(const float* __restrict__ dw,
                             const float* __restrict__ bw,
                             const float* __restrict__ cw)
{
    int id = blockIdx.x * 256 + threadIdx.x;  // 8192
    if (id < EDIM * DTR) {
        int k = id >> 4, n = id & 15;
        g_dwT[n * EDIM + k] = dw[id];
        g_bwT[n * EDIM + k] = bw[id];
        g_cwT[n * EDIM + k] = cw[id];
    }
}

__global__ void proj3_kernel(const float* __restrict__ db,
                             const float* __restrict__ bb,
                             const float* __restrict__ cb)
{
    int r = blockIdx.x * 16 + (threadIdx.x >> 4);
    int n = threadIdx.x & 15;
    const float4* a4 = (const float4*)(g_x1 + (size_t)r * EDIM);
    const float4* d4 = (const float4*)(g_dwT + n * EDIM);
    const float4* b4 = (const float4*)(g_bwT + n * EDIM);
    const float4* c4 = (const float4*)(g_cwT + n * EDIM);
    float ad = 0, ab = 0, ac = 0;
#pragma unroll 4
    for (int k = 0; k < EDIM / 4; k++) {
        float4 a = a4[k];
        float4 d = d4[k], b = b4[k], c = c4[k];
        ad = fmaf(a.x, d.x, fmaf(a.y, d.y, fmaf(a.z, d.z, fmaf(a.w, d.w, ad))));
        ab = fmaf(a.x, b.x, fmaf(a.y, b.y, fmaf(a.z, b.z, fmaf(a.w, b.w, ab))));
        ac = fmaf(a.x, c.x, fmaf(a.y, c.y, fmaf(a.z, c.z, fmaf(a.w, c.w, ac))));
    }
    size_t o = (size_t)r * 16 + n;
    g_d1[o] = ad + db[n];
    g_Bm[o] = ab + bb[n];
    g_Cm[o] = ac + cb[n];
}

__global__ void dtsp_kernel(const float* __restrict__ dtw,
                            const float* __restrict__ dtb)
{
    size_t id = (size_t)blockIdx.x * 256 + threadIdx.x;  // NT*512
    size_t r = id >> 9;
    int e = (int)(id & 511);
    const float* d1r = g_d1 + r * 16;
    float acc = dtb[e];
#pragma unroll
    for (int k = 0; k < 16; k++)
        acc = fmaf(d1r[k], dtw[k * EDIM + e], acc);
    g_delta[id] = fast_softplus(acc);
}

// Selective scan; writes y directly as bf16 hi/lo split into g_c1h/g_c1l
__global__ void __launch_bounds__(512) scan_kernel(
    const float* __restrict__ A_log, const float* __restrict__ D_vec)
{
    int n = blockIdx.x;
    int e = threadIdx.x;  // 0..511
    float A[SDIM], h[SDIM];
#pragma unroll
    for (int s = 0; s < SDIM; s++) {
        A[s] = -fast_exp(A_log[e * SDIM + s]);
        h[s] = 0.0f;
    }
    float Dv = D_vec[e];
    __shared__ float sbv[SDIM], scv[SDIM];
    for (int t = 0; t < TSTEP; t++) {
        size_t r = (size_t)n * TSTEP + t;
        if (e < 16)       sbv[e]      = g_Bm[r * 16 + e];
        else if (e < 32)  scv[e - 16] = g_Cm[r * 16 + (e - 16)];
        __syncthreads();
        float dt = g_delta[r * EDIM + e];
        float xt = g_x1[r * EDIM + e];
        float dx = dt * xt;
        float yv = 0.0f;
#pragma unroll
        for (int s = 0; s < SDIM; s++) {
            h[s] = fmaf(fast_exp(dt * A[s]), h[s], dx * sbv[s]);
            yv   = fmaf(scv[s], h[s], yv);
        }
        yv += xt * Dv;
        float g = g_xp[r * 1024 + EDIM + e];
        yv *= g * fast_sigmoid(g);
        __nv_bfloat16 hi, lo; bsplit(yv, hi, lo);
        g_c1h[r * EDIM + e] = hi;
        g_c1l[r * EDIM + e] = lo;
        __syncthreads();
    }
}

// outs = mb (n-major) + x2 (t-major) residual; also split for q/k GEMM input
__global__ void write_outs_split(float* __restrict__ outs) {
    int ro = blockIdx.x;               // t*N + n
    int tid = threadIdx.x;
    int t = ro >> 10, n = ro & 1023;
    float v = g_mb[((size_t)n * TSTEP + t) * HDIM + tid]
            + g_x2[(size_t)ro * HDIM + tid];
    size_t dst = (size_t)ro * HDIM + tid;
    outs[dst] = v;
    __nv_bfloat16 h, l; bsplit(v, h, l);
    g_xh[dst] = h; g_xl[dst] = l;
}

// ===========================================================================
// Host launch
// ===========================================================================
#define GEMM_SMEM 65536

extern "C" void kernel_launch(void* const* d_in, const int* in_sizes, int n_in,
                              void* d_out, int out_size)
{
    const float* adj     = (const float*)d_in[0];
    const float* msg1_w  = (const float*)d_in[1];
    const float* msg1_b  = (const float*)d_in[2];
    const float* upd1_w  = (const float*)d_in[3];
    const float* upd1_b  = (const float*)d_in[4];
    const float* ln1_g   = (const float*)d_in[5];
    const float* ln1_b   = (const float*)d_in[6];
    const float* msg2_w  = (const float*)d_in[7];
    const float* msg2_b  = (const float*)d_in[8];
    const float* upd2_w  = (const float*)d_in[9];
    const float* upd2_b  = (const float*)d_in[10];
    const float* ln2_g   = (const float*)d_in[11];
    const float* ln2_b   = (const float*)d_in[12];
    const float* mbln_g  = (const float*)d_in[13];
    const float* mbln_b  = (const float*)d_in[14];
    const float* in_w    = (const float*)d_in[15];
    const float* in_b    = (const float*)d_in[16];
    const float* delta_w = (const float*)d_in[17];
    const float* delta_b = (const float*)d_in[18];
    const float* dt_w    = (const float*)d_in[19];
    const float* dt_b    = (const float*)d_in[20];
    const float* Bp_w    = (const float*)d_in[21];
    const float* Bp_b    = (const float*)d_in[22];
    const float* Cp_w    = (const float*)d_in[23];
    const float* Cp_b    = (const float*)d_in[24];
    const float* A_log   = (const float*)d_in[25];
    const float* D_vec   = (const float*)d_in[26];
    const float* out_w   = (const float*)d_in[27];
    const float* out_b   = (const float*)d_in[28];
    const float* q_w     = (const float*)d_in[29];
    const float* k_w     = (const float*)d_in[30];
    const float* gate_b  = (const float*)d_in[31];

    float* out    = (float*)d_out;
    float* outs   = out;                                    // [T,N,H]
    float* probs  = out + (size_t)TSTEP * NNODE * HDIM;     // [T,N,N]
    float* logits = probs + (size_t)TSTEP * NNODE * NNODE;  // [T,N,N]

    cudaFuncSetAttribute(gemm3x, cudaFuncAttributeMaxDynamicSharedMemorySize,
                         GEMM_SMEM);

    float *pe_, *m1_, *x_, *agg_, *m2_, *x2_, *xp_, *mb_;
    __nv_bfloat16 *c1h_, *c1l_, *xh_, *xl_, *qh_, *ql_, *kh_, *kl_, *wh_, *wl_;
    cudaGetSymbolAddress((void**)&pe_,  g_pe);
    cudaGetSymbolAddress((void**)&m1_,  g_m1);
    cudaGetSymbolAddress((void**)&x_,   g_x);
    cudaGetSymbolAddress((void**)&agg_, g_agg);
    cudaGetSymbolAddress((void**)&m2_,  g_m2);
    cudaGetSymbolAddress((void**)&x2_,  g_x2);
    cudaGetSymbolAddress((void**)&xp_,  g_xp);
    cudaGetSymbolAddress((void**)&mb_,  g_mb);
    cudaGetSymbolAddress((void**)&c1h_, g_c1h);
    cudaGetSymbolAddress((void**)&c1l_, g_c1l);
    cudaGetSymbolAddress((void**)&xh_,  g_xh);
    cudaGetSymbolAddress((void**)&xl_,  g_xl);
    cudaGetSymbolAddress((void**)&qh_,  g_qh);
    cudaGetSymbolAddress((void**)&ql_,  g_ql);
    cudaGetSymbolAddress((void**)&kh_,  g_kh);
    cudaGetSymbolAddress((void**)&kl_,  g_kl);
    cudaGetSymbolAddress((void**)&wh_,  g_wh);
    cudaGetSymbolAddress((void**)&wl_,  g_wl);

    // 1. PE + m1 (tiny SIMT GEMM)
    pe_kernel<<<NNODE, 128>>>();
    sgemm_nn<<<dim3(HDIM / 128, NNODE / 128), 256>>>(pe_, msg1_w, msg1_b, m1_,
                                                     NNODE, HDIM, PDIM);
    // 2. layer 1: agg1, concat+split, upd1 GEMM, relu+LN (+split for msg2)
    agg_kernel<<<dim3(NNODE, TSTEP), 256>>>(adj, m1_, agg_, 0);
    concat1_split<<<(NT * 512) / 256, 256>>>();
    split_wT<<<(512 * 256 + 255) / 256, 256>>>(upd1_w, 512, 256);
    gemm3x<<<dim3(2, NT / 128), 256, GEMM_SMEM>>>(
        c1h_, c1l_, wh_, wl_, upd1_b, x_, nullptr, nullptr, 512, 256, 0, 0, 0, 0);
    relu_ln_kernel<<<NT, 256>>>(x_, ln1_g, ln1_b, x_, 1);
    // 3. layer 2: m2 GEMM, agg2, concat+split, upd2 GEMM, relu+LN
    split_wT<<<(256 * 256 + 255) / 256, 256>>>(msg2_w, 256, 256);
    gemm3x<<<dim3(2, NT / 128), 256, GEMM_SMEM>>>(
        xh_, xl_, wh_, wl_, msg2_b, m2_, nullptr, nullptr, 256, 256, 0, 0, 0, 0);
    agg_kernel<<<dim3(NNODE, TSTEP), 256>>>(adj, m2_, agg_, 1);
    concat2_split<<<(NT * 512) / 256, 256>>>();
    split_wT<<<(512 * 256 + 255) / 256, 256>>>(upd2_w, 512, 256);
    gemm3x<<<dim3(2, NT / 128), 256, GEMM_SMEM>>>(
        c1h_, c1l_, wh_, wl_, upd2_b, x2_, nullptr, nullptr, 512, 256, 0, 0, 0, 0);
    relu_ln_kernel<<<NT, 256>>>(x2_, ln2_g, ln2_b, x2_, 0);
    // 4. Mamba: LN+transpose+split -> xn; in_proj GEMM; silu
    ln_seq_split<<<NT, 256>>>(mbln_g, mbln_b);
    split_wT<<<(256 * 1024 + 255) / 256, 256>>>(in_w, 256, 1024);
    gemm3x<<<dim3(8, NT / 128), 256, GEMM_SMEM>>>(
        xh_, xl_, wh_, wl_, in_b, xp_, nullptr, nullptr, 256, 1024, 0, 0, 0, 0);
    silu_kernel<<<(NT * EDIM) / 256, 256>>>();
    // 5. small projections + dt softplus
    transpose_w3<<<(EDIM * DTR + 255) / 256, 256>>>(delta_w, Bp_w, Cp_w);
    proj3_kernel<<<NT / 16, 256>>>(delta_b, Bp_b, Cp_b);
    dtsp_kernel<<<(NT * EDIM) / 256, 256>>>(dt_w, dt_b);
    // 6. scan (writes y split into c1h/c1l)
    scan_kernel<<<NNODE, EDIM>>>(A_log, D_vec);
    // 7. out projection + residual -> outs; split for q/k
    split_wT<<<(512 * 256 + 255) / 256, 256>>>(out_w, 512, 256);
    gemm3x<<<dim3(2, NT / 128), 256, GEMM_SMEM>>>(
        c1h_, c1l_, wh_, wl_, out_b, mb_, nullptr, nullptr, 512, 256, 0, 0, 0, 0);
    write_outs_split<<<NT, 256>>>(outs);
    // 8. q/k GEMMs with bf16-split epilogue, then fused score head
    split_wT<<<(256 * 256 + 255) / 256, 256>>>(q_w, 256, 256);
    gemm3x<<<dim3(2, NT / 128), 256, GEMM_SMEM>>>(
        xh_, xl_, wh_, wl_, nullptr, qh_, ql_, nullptr, 256, 256, 2, 0, 0, 0);
    split_wT<<<(256 * 256 + 255) / 256, 256>>>(k_w, 256, 256);
    gemm3x<<<dim3(2, NT / 128), 256, GEMM_SMEM>>>(
        xh_, xl_, wh_, wl_, nullptr, kh_, kl_, nullptr, 256, 256, 2, 0, 0, 0);
    gemm3x<<<dim3(8, 8, TSTEP), 256, GEMM_SMEM>>>(
        qh_, ql_, kh_, kl_, nullptr, probs, logits, gate_b, 256, 1024, 1,
        (size_t)NNODE * HDIM, (size_t)NNODE * HDIM, (size_t)NNODE * NNODE);
}

// round 6
// speedup vs baseline: 1.6017x; 1.0292x over previous
#include <cuda_runtime.h>
#include <cuda_bf16.h>
#include <cstdint>

// Problem constants
#define NNODE 1024
#define TSTEP 32
#define HDIM  256
#define PDIM  256
#define EDIM  512
#define DTR   16
#define SDIM  16
#define NT    (NNODE * TSTEP)   // 32768

#define SMEM_SWIZZLE_128B(byte_offset) \
    ((byte_offset) ^ (((byte_offset) >> 3) & 0x70))

// ===========================================================================
// Scratch (device globals)
// ===========================================================================
__device__ float g_pe   [NNODE * PDIM];
__device__ float g_m1   [NNODE * HDIM];
__device__ float g_x    [(size_t)NT * HDIM];
__device__ float g_m2   [(size_t)NT * HDIM];
__device__ float g_x2   [(size_t)NT * HDIM];
__device__ float g_xp   [(size_t)NT * 1024];
__device__ float g_x1   [(size_t)NT * EDIM];
__device__ float g_delta[(size_t)NT * EDIM];
__device__ float g_d1   [(size_t)NT * DTR];
__device__ float g_Bm   [(size_t)NT * SDIM];
__device__ float g_Cm   [(size_t)NT * SDIM];
__device__ float g_mb   [(size_t)NT * HDIM];
__device__ float g_dwT  [DTR * EDIM];
__device__ float g_bwT  [DTR * EDIM];
__device__ float g_cwT  [DTR * EDIM];
// bf16 hi/lo split buffers
__device__ __nv_bfloat16 g_c1h[(size_t)NT * 512];
__device__ __nv_bfloat16 g_c1l[(size_t)NT * 512];
__device__ __nv_bfloat16 g_xh [(size_t)NT * HDIM];
__device__ __nv_bfloat16 g_xl [(size_t)NT * HDIM];
__device__ __nv_bfloat16 g_qh [(size_t)NT * HDIM];
__device__ __nv_bfloat16 g_ql [(size_t)NT * HDIM];
__device__ __nv_bfloat16 g_kh [(size_t)NT * HDIM];
__device__ __nv_bfloat16 g_kl [(size_t)NT * HDIM];
__device__ __nv_bfloat16 g_wh [1024 * 512];
__device__ __nv_bfloat16 g_wl [1024 * 512];

__device__ __forceinline__ void bsplit(float v, __nv_bfloat16& h, __nv_bfloat16& l) {
    h = __float2bfloat16(v);
    l = __float2bfloat16(v - __bfloat162float(h));
}

// ===========================================================================
// Fast math (FMA-pipe exp)
// ===========================================================================
__device__ __forceinline__ float fast_exp(float x) {
    x = fminf(fmaxf(x, -87.0f), 87.0f);
    float y = x * 1.44269504088896340736f;
    float t = y + 12582912.0f;
    int   e = __float_as_int(t) - 0x4B400000;
    float r = t - 12582912.0f;
    float f = (y - r) * 0.69314718055994530942f;
    float p = 1.3888889e-3f;
    p = fmaf(p, f, 8.3333333e-3f);
    p = fmaf(p, f, 4.1666668e-2f);
    p = fmaf(p, f, 1.6666667e-1f);
    p = fmaf(p, f, 0.5f);
    p = fmaf(p, f, 1.0f);
    p = fmaf(p, f, 1.0f);
    float s = __int_as_float((e + 127) << 23);
    return p * s;
}
__device__ __forceinline__ float fast_sigmoid(float x) {
    return 1.0f / (1.0f + fast_exp(-x));
}
__device__ __forceinline__ float fast_softplus(float x) {
    if (x > 20.0f) return x;
    return log1pf(fast_exp(x));
}

// ===========================================================================
// Warp MMA / async-copy primitives (baseline sm_80+ only)
// ===========================================================================
__device__ __forceinline__ uint32_t smem_u32(const void* p) {
    uint32_t a;
    asm("{ .reg .u64 t; cvta.to.shared.u64 t, %1; cvt.u32.u64 %0, t; }"
        : "=r"(a) : "l"(p));
    return a;
}
__device__ __forceinline__ void ldsm_x4(uint32_t* r, uint32_t addr) {
    asm volatile("ldmatrix.sync.aligned.m8n8.x4.shared.b16 {%0,%1,%2,%3}, [%4];"
        : "=r"(r[0]), "=r"(r[1]), "=r"(r[2]), "=r"(r[3]) : "r"(addr));
}
__device__ __forceinline__ void mma16816(float* c, const uint32_t* a,
                                         uint32_t b0, uint32_t b1) {
    asm volatile(
        "mma.sync.aligned.m16n8k16.row.col.f32.bf16.bf16.f32 "
        "{%0,%1,%2,%3}, {%4,%5,%6,%7}, {%8,%9}, {%0,%1,%2,%3};"
        : "+f"(c[0]), "+f"(c[1]), "+f"(c[2]), "+f"(c[3])
        : "r"(a[0]), "r"(a[1]), "r"(a[2]), "r"(a[3]), "r"(b0), "r"(b1));
}
__device__ __forceinline__ void cp_async16(uint32_t saddr, const void* gaddr) {
    asm volatile("cp.async.cg.shared.global [%0], [%1], 16;"
        :: "r"(saddr), "l"(gaddr));
}
#define CP_COMMIT()  asm volatile("cp.async.commit_group;" ::: "memory")
#define CP_WAIT(n)   asm volatile("cp.async.wait_group %0;" :: "n"(n) : "memory")

// ===========================================================================
// HMMA 3xBF16 GEMM: C[M,Nc] = A[M,K] @ B[Nc,K]^T  (A,B hi/lo split, fp32 acc)
// 128x128 CTA tile, 4 warps (2M x 2N), warp tile 64x64, K-chunks of 64,
// 2-stage cp.async pipeline, SW128-swizzled smem. 128 threads.
// mode 0: fp32 out (+bias); mode 1: score head (probs+logits);
// mode 2: bf16 hi/lo split output.
// ===========================================================================
__global__ void __launch_bounds__(128, 2) gemm3x(
    const __nv_bfloat16* __restrict__ Ah, const __nv_bfloat16* __restrict__ Al,
    const __nv_bfloat16* __restrict__ Bh, const __nv_bfloat16* __restrict__ Bl,
    const float* __restrict__ bias,
    void* __restrict__ out1, void* __restrict__ out2,
    const float* __restrict__ gb_ptr,
    int K, int Nc, int mode,
    size_t aBatch, size_t bBatch, size_t cBatch)
{
    extern __shared__ __align__(16) char smem[];
    const uint32_t sb = smem_u32(smem);
    const int tid = threadIdx.x;
    const int wid = tid >> 5, lane = tid & 31;
    const int wm = wid & 1, wn = wid >> 1;

    const size_t zA = (size_t)blockIdx.z * aBatch;
    const size_t zB = (size_t)blockIdx.z * bBatch;
    const __nv_bfloat16* Aseg[3] = { Ah + zA, Ah + zA, Al + zA };
    const __nv_bfloat16* Bseg[3] = { Bh + zB, Bl + zB, Bh + zB };

    const int m0 = blockIdx.y * 128, n0 = blockIdx.x * 128;
    const int ksub = K >> 6;           // 64-wide chunks per segment
    const int nk = 3 * ksub;

    float acc[4][8][4];
#pragma unroll
    for (int i = 0; i < 4; i++)
#pragma unroll
        for (int j = 0; j < 8; j++)
#pragma unroll
            for (int r = 0; r < 4; r++) acc[i][j][r] = 0.0f;

    // ldmatrix lane->matrix offsets (same mapping as validated R5 kernel)
    const int a_r = ((lane >> 3) & 1) * 8 + (lane & 7);
    const int a_c = ((lane >> 4) & 1) * 8;
    const int b_n = ((lane >> 4) & 1) * 8 + (lane & 7);
    const int b_k = ((lane >> 3) & 1) * 8;

    auto load_tile = [&](const __nv_bfloat16* g, int row0, int k0, uint32_t sdst) {
#pragma unroll
        for (int j = 0; j < 8; j++) {
            int c = tid + j * 128;          // 0..1023
            int row = c >> 3, ch = c & 7;
            const void* gp = g + (size_t)(row0 + row) * K + k0 + ch * 8;
            uint32_t sp = sdst + SMEM_SWIZZLE_128B((uint32_t)(row * 128 + ch * 16));
            cp_async16(sp, gp);
        }
    };

    // prologue: chunk 0 -> buffer 0
    load_tile(Aseg[0], m0, 0, sb);
    load_tile(Bseg[0], n0, 0, sb + 16384);
    CP_COMMIT();

    for (int i = 0; i < nk; i++) {
        int b = i & 1;
        if (i + 1 < nk) {
            int seg = (i + 1) / ksub;
            int k0 = ((i + 1) - seg * ksub) << 6;
            uint32_t sd = sb + (uint32_t)(b ^ 1) * 32768u;
            load_tile(Aseg[seg], m0, k0, sd);
            load_tile(Bseg[seg], n0, k0, sd + 16384);
            CP_COMMIT();
            CP_WAIT(1);
        } else {
            CP_COMMIT();
            CP_WAIT(0);
        }
        __syncthreads();

        uint32_t abase = sb + (uint32_t)b * 32768u;
        uint32_t bbase = abase + 16384u;
#pragma unroll
        for (int ks = 0; ks < 4; ks++) {
            uint32_t afr[4][4];
#pragma unroll
            for (int mi = 0; mi < 4; mi++) {
                int row = wm * 64 + mi * 16 + a_r;
                int col = ks * 16 + a_c;
                ldsm_x4(afr[mi],
                        abase + SMEM_SWIZZLE_128B((uint32_t)(row * 128 + col * 2)));
            }
            uint32_t bfr[4][4];
#pragma unroll
            for (int j = 0; j < 4; j++) {
                int n = wn * 64 + j * 16 + b_n;
                int kc = ks * 16 + b_k;
                ldsm_x4(bfr[j],
                        bbase + SMEM_SWIZZLE_128B((uint32_t)(n * 128 + kc * 2)));
            }
#pragma unroll
            for (int mi = 0; mi < 4; mi++)
#pragma unroll
                for (int ni = 0; ni < 8; ni++) {
                    const uint32_t* bs = bfr[ni >> 1];
                    mma16816(acc[mi][ni], afr[mi],
                             bs[(ni & 1) * 2], bs[(ni & 1) * 2 + 1]);
                }
        }
        __syncthreads();
    }

    // ---------------- epilogue ----------------
    const int rg = lane >> 2;            // 0..7
    const int cg = (lane & 3) * 2;       // 0,2,4,6
#pragma unroll
    for (int mi = 0; mi < 4; mi++) {
#pragma unroll
        for (int ni = 0; ni < 8; ni++) {
            float* c = acc[mi][ni];
            int gr0 = m0 + wm * 64 + mi * 16 + rg;
            int gc  = n0 + wn * 64 + ni * 8 + cg;
            if (mode == 0) {
                float* C = (float*)out1;
                float b0 = bias ? bias[gc] : 0.0f;
                float b1 = bias ? bias[gc + 1] : 0.0f;
                *(float2*)(C + (size_t)gr0 * Nc + gc)       = {c[0] + b0, c[1] + b1};
                *(float2*)(C + (size_t)(gr0 + 8) * Nc + gc) = {c[2] + b0, c[3] + b1};
            } else if (mode == 1) {
                float gb = *gb_ptr;
                float* P = (float*)out1 + (size_t)blockIdx.z * cBatch;
                float* L = (float*)out2 + (size_t)blockIdx.z * cBatch;
                float l0 = c[0] * 0.0625f + gb, l1 = c[1] * 0.0625f + gb;
                float l2 = c[2] * 0.0625f + gb, l3 = c[3] * 0.0625f + gb;
                *(float2*)(L + (size_t)gr0 * Nc + gc)       = {l0, l1};
                *(float2*)(L + (size_t)(gr0 + 8) * Nc + gc) = {l2, l3};
                *(float2*)(P + (size_t)gr0 * Nc + gc)       =
                    {fast_sigmoid(l0), fast_sigmoid(l1)};
                *(float2*)(P + (size_t)(gr0 + 8) * Nc + gc) =
                    {fast_sigmoid(l2), fast_sigmoid(l3)};
            } else {  // mode 2: bf16 hi/lo split
                __nv_bfloat16* H  = (__nv_bfloat16*)out1;
                __nv_bfloat16* Lo = (__nv_bfloat16*)out2;
                __nv_bfloat16 h0, l0, h1, l1;
                bsplit(c[0], h0, l0); bsplit(c[1], h1, l1);
                *(__nv_bfloat162*)(H  + (size_t)gr0 * Nc + gc) = {h0, h1};
                *(__nv_bfloat162*)(Lo + (size_t)gr0 * Nc + gc) = {l0, l1};
                bsplit(c[2], h0, l0); bsplit(c[3], h1, l1);
                *(__nv_bfloat162*)(H  + (size_t)(gr0 + 8) * Nc + gc) = {h0, h1};
                *(__nv_bfloat162*)(Lo + (size_t)(gr0 + 8) * Nc + gc) = {l0, l1};
            }
        }
    }
}

// ===========================================================================
// Small SIMT SGEMM (tiny m1 = pe @ msg1_w only)
// ===========================================================================
__global__ void __launch_bounds__(256) sgemm_nn(
    const float* __restrict__ A, const float* __restrict__ B,
    const float* __restrict__ bias, float* __restrict__ C,
    int M, int Nc, int K)
{
    __shared__ float As[8][128];
    __shared__ float Bs[8][128];
    int tid = threadIdx.x;
    int bx = blockIdx.x, by = blockIdx.y;
    int tx = tid & 15, ty = tid >> 4;
    int arow = tid >> 1, acol = (tid & 1) * 4;
    int brow = tid >> 5, bcol = (tid & 31) * 4;
    const float* Ab = A + (size_t)by * 128 * K;
    const float* Bb = B + (size_t)bx * 128;
    float acc[8][8] = {};
    for (int k0 = 0; k0 < K; k0 += 8) {
        float4 av = *(const float4*)(Ab + (size_t)arow * K + k0 + acol);
        As[acol + 0][arow] = av.x; As[acol + 1][arow] = av.y;
        As[acol + 2][arow] = av.z; As[acol + 3][arow] = av.w;
        *(float4*)&Bs[brow][bcol] =
            *(const float4*)(Bb + (size_t)(k0 + brow) * Nc + bcol);
        __syncthreads();
#pragma unroll
        for (int kk = 0; kk < 8; kk++) {
            float4 a0 = *(float4*)&As[kk][ty * 8];
            float4 a1 = *(float4*)&As[kk][ty * 8 + 4];
            float4 b0 = *(float4*)&Bs[kk][tx * 8];
            float4 b1 = *(float4*)&Bs[kk][tx * 8 + 4];
            float ar[8] = {a0.x, a0.y, a0.z, a0.w, a1.x, a1.y, a1.z, a1.w};
            float br[8] = {b0.x, b0.y, b0.z, b0.w, b1.x, b1.y, b1.z, b1.w};
#pragma unroll
            for (int i = 0; i < 8; i++)
#pragma unroll
                for (int j = 0; j < 8; j++)
                    acc[i][j] = fmaf(ar[i], br[j], acc[i][j]);
        }
        __syncthreads();
    }
#pragma unroll
    for (int i = 0; i < 8; i++) {
        int r = by * 128 + ty * 8 + i;
#pragma unroll
        for (int j = 0; j < 8; j += 4) {
            int c = bx * 128 + tx * 8 + j;
            float4 v;
            v.x = acc[i][j] + bias[c];         v.y = acc[i][j + 1] + bias[c + 1];
            v.z = acc[i][j + 2] + bias[c + 2]; v.w = acc[i][j + 3] + bias[c + 3];
            *(float4*)(C + (size_t)r * Nc + c) = v;
        }
    }
}

// ===========================================================================
// Elementwise / helper kernels
// ===========================================================================
__global__ void pe_kernel() {
    int n = blockIdx.x;
    int i = threadIdx.x;  // 0..127
    float div = expf((float)(2 * i) * (-0.03597867333f));
    float ang = (float)n * div;
    g_pe[n * PDIM + 2 * i]     = sinf(ang);
    g_pe[n * PDIM + 2 * i + 1] = cosf(ang);
}

// broadcast pe split into c-buffer cols [0,256) for every row (t-major)
__global__ void pe_bcast_split() {
    int r = blockIdx.x;            // t*N + n
    int c = threadIdx.x;           // 0..255
    float v = g_pe[(size_t)(r & 1023) * PDIM + c];
    __nv_bfloat16 h, l; bsplit(v, h, l);
    size_t id = (size_t)r * 512 + c;
    g_c1h[id] = h; g_c1l[id] = l;
}

// weight transpose+split: W[K,N] fp32 -> g_wh/g_wl [N,K] bf16
__global__ void split_wT(const float* __restrict__ W, int K, int N) {
    int i = blockIdx.x * 256 + threadIdx.x;
    if (i < K * N) {
        int k = i / N, n = i % N;
        __nv_bfloat16 h, l; bsplit(W[i], h, l);
        g_wh[(size_t)n * K + k] = h;
        g_wl[(size_t)n * K + k] = l;
    }
}

// Sparse aggregation: c1[t,i, 256+h] = split(sum_j adj[t,i,j] * m[(t,)j,h])
__global__ void agg_split_kernel(const float* __restrict__ adj,
                                 const float* __restrict__ m, int per_t)
{
    int i = blockIdx.x, t = blockIdx.y;
    const float* arow = adj + ((size_t)t * NNODE + i) * NNODE;
    __shared__ int s_idx[NNODE];
    __shared__ int s_cnt;
    if (threadIdx.x == 0) s_cnt = 0;
    __syncthreads();
    for (int j = threadIdx.x; j < NNODE; j += 256) {
        if (arow[j] != 0.0f) {
            int p = atomicAdd(&s_cnt, 1);
            s_idx[p] = j;
        }
    }
    __syncthreads();
    int cnt = s_cnt;
    int h = threadIdx.x;
    const float* mb = m + (per_t ? (size_t)t * NNODE * HDIM : 0);
    float acc = 0.0f;
    for (int p = 0; p < cnt; p++)
        acc += mb[(size_t)s_idx[p] * HDIM + h];
    __nv_bfloat16 hi, lo; bsplit(acc, hi, lo);
    size_t id = ((size_t)t * NNODE + i) * 512 + 256 + h;
    g_c1h[id] = hi; g_c1l[id] = lo;
}

// ReLU + LN; optional bf16 split to xh/xl and/or c-buffer cols [0,256)
__global__ void relu_ln_kernel(const float* __restrict__ in,
                               const float* __restrict__ gam,
                               const float* __restrict__ bet,
                               float* __restrict__ out,
                               int to_xhl, int to_cbuf)
{
    int row = blockIdx.x, tid = threadIdx.x;
    float v = fmaxf(in[(size_t)row * HDIM + tid], 0.0f);
    float s = v, q = v * v;
#pragma unroll
    for (int o = 16; o > 0; o >>= 1) {
        s += __shfl_xor_sync(0xffffffffu, s, o);
        q += __shfl_xor_sync(0xffffffffu, q, o);
    }
    __shared__ float ss[8], qq[8];
    __shared__ float s_mu, s_rstd;
    int w = tid >> 5;
    if ((tid & 31) == 0) { ss[w] = s; qq[w] = q; }
    __syncthreads();
    if (tid == 0) {
        float S = 0, QQ = 0;
        for (int i = 0; i < 8; i++) { S += ss[i]; QQ += qq[i]; }
        float mu = S * (1.0f / 256.0f);
        float var = QQ * (1.0f / 256.0f) - mu * mu;
        s_mu = mu; s_rstd = rsqrtf(var + 1e-5f);
    }
    __syncthreads();
    float o = (v - s_mu) * s_rstd * gam[tid] + bet[tid];
    out[(size_t)row * HDIM + tid] = o;
    __nv_bfloat16 h, l; bsplit(o, h, l);
    if (to_xhl) {
        g_xh[(size_t)row * HDIM + tid] = h;
        g_xl[(size_t)row * HDIM + tid] = l;
    }
    if (to_cbuf) {
        size_t id = (size_t)row * 512 + tid;
        g_c1h[id] = h; g_c1l[id] = l;
    }
}

// Mamba pre-LN: read x2 (t-major), write bf16 split xn (n-major)
__global__ void ln_seq_split(const float* __restrict__ gam,
                             const float* __restrict__ bet)
{
    int rin = blockIdx.x;              // t*N + n
    int tid = threadIdx.x;
    int t = rin >> 10, n = rin & 1023;
    float v = g_x2[(size_t)rin * HDIM + tid];
    float s = v, q = v * v;
#pragma unroll
    for (int o = 16; o > 0; o >>= 1) {
        s += __shfl_xor_sync(0xffffffffu, s, o);
        q += __shfl_xor_sync(0xffffffffu, q, o);
    }
    __shared__ float ss[8], qq[8];
    __shared__ float s_mu, s_rstd;
    int w = tid >> 5;
    if ((tid & 31) == 0) { ss[w] = s; qq[w] = q; }
    __syncthreads();
    if (tid == 0) {
        float S = 0, QQ = 0;
        for (int i = 0; i < 8; i++) { S += ss[i]; QQ += qq[i]; }
        float mu = S * (1.0f / 256.0f);
        float var = QQ * (1.0f / 256.0f) - mu * mu;
        s_mu = mu; s_rstd = rsqrtf(var + 1e-5f);
    }
    __syncthreads();
    float o = (v - s_mu) * s_rstd * gam[tid] + bet[tid];
    size_t dst = ((size_t)n * TSTEP + t) * HDIM + tid;
    __nv_bfloat16 h, l; bsplit(o, h, l);
    g_xh[dst] = h; g_xl[dst] = l;
}

__global__ void silu_kernel() {
    size_t id = (size_t)blockIdx.x * 256 + threadIdx.x;  // NT*512
    size_t r = id >> 9, e = id & 511;
    float v = g_xp[r * 1024 + e];
    g_x1[id] = v * fast_sigmoid(v);
}

__global__ void transpose_w3(const float* __restrict__ dw,
                             const float* __restrict__ bw,
                             const float* __restrict__ cw)
{
    int id = blockIdx.x * 256 + threadIdx.x;  // 8192
    if (id < EDIM * DTR) {
        int k = id >> 4, n = id & 15;
        g_dwT[n * EDIM + k] = dw[id];
        g_bwT[n * EDIM + k] = bw[id];
        g_cwT[n * EDIM + k] = cw[id];
    }
}

__global__ void proj3_kernel(const float* __restrict__ db,
                             const float* __restrict__ bb,
                             const float* __restrict__ cb)
{
    int r = blockIdx.x * 16 + (threadIdx.x >> 4);
    int n = threadIdx.x & 15;
    const float4* a4 = (const float4*)(g_x1 + (size_t)r * EDIM);
    const float4* d4 = (const float4*)(g_dwT + n * EDIM);
    const float4* b4 = (const float4*)(g_bwT + n * EDIM);
    const float4* c4 = (const float4*)(g_cwT + n * EDIM);
    float ad = 0, ab = 0, ac = 0;
#pragma unroll 4
    for (int k = 0; k < EDIM / 4; k++) {
        float4 a = a4[k];
        float4 d = d4[k], b = b4[k], c = c4[k];
        ad = fmaf(a.x, d.x, fmaf(a.y, d.y, fmaf(a.z, d.z, fmaf(a.w, d.w, ad))));
        ab = fmaf(a.x, b.x, fmaf(a.y, b.y, fmaf(a.z, b.z, fmaf(a.w, b.w, ab))));
        ac = fmaf(a.x, c.x, fmaf(a.y, c.y, fmaf(a.z, c.z, fmaf(a.w, c.w, ac))));
    }
    size_t o = (size_t)r * 16 + n;
    g_d1[o] = ad + db[n];
    g_Bm[o] = ab + bb[n];
    g_Cm[o] = ac + cb[n];
}

__global__ void dtsp_kernel(const float* __restrict__ dtw,
                            const float* __restrict__ dtb)
{
    size_t id = (size_t)blockIdx.x * 256 + threadIdx.x;  // NT*512
    size_t r = id >> 9;
    int e = (int)(id & 511);
    const float* d1r = g_d1 + r * 16;
    float acc = dtb[e];
#pragma unroll
    for (int k = 0; k < 16; k++)
        acc = fmaf(d1r[k], dtw[k * EDIM + e], acc);
    g_delta[id] = fast_softplus(acc);
}

// Selective scan; writes y directly as bf16 hi/lo split into g_c1h/g_c1l
__global__ void __launch_bounds__(512) scan_kernel(
    const float* __restrict__ A_log, const float* __restrict__ D_vec)
{
    int n = blockIdx.x;
    int e = threadIdx.x;  // 0..511
    float A[SDIM], h[SDIM];
#pragma unroll
    for (int s = 0; s < SDIM; s++) {
        A[s] = -fast_exp(A_log[e * SDIM + s]);
        h[s] = 0.0f;
    }
    float Dv = D_vec[e];
    __shared__ float sbv[SDIM], scv[SDIM];
    for (int t = 0; t < TSTEP; t++) {
        size_t r = (size_t)n * TSTEP + t;
        if (e < 16)       sbv[e]      = g_Bm[r * 16 + e];
        else if (e < 32)  scv[e - 16] = g_Cm[r * 16 + (e - 16)];
        __syncthreads();
        float dt = g_delta[r * EDIM + e];
        float xt = g_x1[r * EDIM + e];
        float dx = dt * xt;
        float yv = 0.0f;
#pragma unroll
        for (int s = 0; s < SDIM; s++) {
            h[s] = fmaf(fast_exp(dt * A[s]), h[s], dx * sbv[s]);
            yv   = fmaf(scv[s], h[s], yv);
        }
        yv += xt * Dv;
        float g = g_xp[r * 1024 + EDIM + e];
        yv *= g * fast_sigmoid(g);
        __nv_bfloat16 hi, lo; bsplit(yv, hi, lo);
        g_c1h[r * EDIM + e] = hi;
        g_c1l[r * EDIM + e] = lo;
        __syncthreads();
    }
}

// outs = mb (n-major) + x2 (t-major) residual; also split for q/k GEMM input
__global__ void write_outs_split(float* __restrict__ outs) {
    int ro = blockIdx.x;               // t*N + n
    int tid = threadIdx.x;
    int t = ro >> 10, n = ro & 1023;
    float v = g_mb[((size_t)n * TSTEP + t) * HDIM + tid]
            + g_x2[(size_t)ro * HDIM + tid];
    size_t dst = (size_t)ro * HDIM + tid;
    outs[dst] = v;
    __nv_bfloat16 h, l; bsplit(v, h, l);
    g_xh[dst] = h; g_xl[dst] = l;
}

// ===========================================================================
// Host launch
// ===========================================================================
#define GEMM_SMEM 65536

extern "C" void kernel_launch(void* const* d_in, const int* in_sizes, int n_in,
                              void* d_out, int out_size)
{
    const float* adj     = (const float*)d_in[0];
    const float* msg1_w  = (const float*)d_in[1];
    const float* msg1_b  = (const float*)d_in[2];
    const float* upd1_w  = (const float*)d_in[3];
    const float* upd1_b  = (const float*)d_in[4];
    const float* ln1_g   = (const float*)d_in[5];
    const float* ln1_b   = (const float*)d_in[6];
    const float* msg2_w  = (const float*)d_in[7];
    const float* msg2_b  = (const float*)d_in[8];
    const float* upd2_w  = (const float*)d_in[9];
    const float* upd2_b  = (const float*)d_in[10];
    const float* ln2_g   = (const float*)d_in[11];
    const float* ln2_b   = (const float*)d_in[12];
    const float* mbln_g  = (const float*)d_in[13];
    const float* mbln_b  = (const float*)d_in[14];
    const float* in_w    = (const float*)d_in[15];
    const float* in_b    = (const float*)d_in[16];
    const float* delta_w = (const float*)d_in[17];
    const float* delta_b = (const float*)d_in[18];
    const float* dt_w    = (const float*)d_in[19];
    const float* dt_b    = (const float*)d_in[20];
    const float* Bp_w    = (const float*)d_in[21];
    const float* Bp_b    = (const float*)d_in[22];
    const float* Cp_w    = (const float*)d_in[23];
    const float* Cp_b    = (const float*)d_in[24];
    const float* A_log   = (const float*)d_in[25];
    const float* D_vec   = (const float*)d_in[26];
    const float* out_w   = (const float*)d_in[27];
    const float* out_b   = (const float*)d_in[28];
    const float* q_w     = (const float*)d_in[29];
    const float* k_w     = (const float*)d_in[30];
    const float* gate_b  = (const float*)d_in[31];

    float* out    = (float*)d_out;
    float* outs   = out;                                    // [T,N,H]
    float* probs  = out + (size_t)TSTEP * NNODE * HDIM;     // [T,N,N]
    float* logits = probs + (size_t)TSTEP * NNODE * NNODE;  // [T,N,N]

    cudaFuncSetAttribute(gemm3x, cudaFuncAttributeMaxDynamicSharedMemorySize,
                         GEMM_SMEM);

    float *pe_, *m1_, *x_, *m2_, *x2_, *xp_, *mb_;
    __nv_bfloat16 *c1h_, *c1l_, *xh_, *xl_, *qh_, *ql_, *kh_, *kl_, *wh_, *wl_;
    cudaGetSymbolAddress((void**)&pe_,  g_pe);
    cudaGetSymbolAddress((void**)&m1_,  g_m1);
    cudaGetSymbolAddress((void**)&x_,   g_x);
    cudaGetSymbolAddress((void**)&m2_,  g_m2);
    cudaGetSymbolAddress((void**)&x2_,  g_x2);
    cudaGetSymbolAddress((void**)&xp_,  g_xp);
    cudaGetSymbolAddress((void**)&mb_,  g_mb);
    cudaGetSymbolAddress((void**)&c1h_, g_c1h);
    cudaGetSymbolAddress((void**)&c1l_, g_c1l);
    cudaGetSymbolAddress((void**)&xh_,  g_xh);
    cudaGetSymbolAddress((void**)&xl_,  g_xl);
    cudaGetSymbolAddress((void**)&qh_,  g_qh);
    cudaGetSymbolAddress((void**)&ql_,  g_ql);
    cudaGetSymbolAddress((void**)&kh_,  g_kh);
    cudaGetSymbolAddress((void**)&kl_,  g_kl);
    cudaGetSymbolAddress((void**)&wh_,  g_wh);
    cudaGetSymbolAddress((void**)&wl_,  g_wl);

    // 1. PE + m1 (tiny SIMT GEMM)
    pe_kernel<<<NNODE, 128>>>();
    sgemm_nn<<<dim3(HDIM / 128, NNODE / 128), 256>>>(pe_, msg1_w, msg1_b, m1_,
                                                     NNODE, HDIM, PDIM);
    // 2. layer 1: producers write split c-buffer directly; upd1 GEMM; relu+LN
    pe_bcast_split<<<NT, 256>>>();
    agg_split_kernel<<<dim3(NNODE, TSTEP), 256>>>(adj, m1_, 0);
    split_wT<<<(512 * 256 + 255) / 256, 256>>>(upd1_w, 512, 256);
    gemm3x<<<dim3(2, NT / 128), 128, GEMM_SMEM>>>(
        c1h_, c1l_, wh_, wl_, upd1_b, x_, nullptr, nullptr, 512, 256, 0, 0, 0, 0);
    relu_ln_kernel<<<NT, 256>>>(x_, ln1_g, ln1_b, x_, 1, 1);
    // 3. layer 2: m2 GEMM; agg2 split into c-buffer; upd2 GEMM; relu+LN
    split_wT<<<(256 * 256 + 255) / 256, 256>>>(msg2_w, 256, 256);
    gemm3x<<<dim3(2, NT / 128), 128, GEMM_SMEM>>>(
        xh_, xl_, wh_, wl_, msg2_b, m2_, nullptr, nullptr, 256, 256, 0, 0, 0, 0);
    agg_split_kernel<<<dim3(NNODE, TSTEP), 256>>>(adj, m2_, 1);
    split_wT<<<(512 * 256 + 255) / 256, 256>>>(upd2_w, 512, 256);
    gemm3x<<<dim3(2, NT / 128), 128, GEMM_SMEM>>>(
        c1h_, c1l_, wh_, wl_, upd2_b, x2_, nullptr, nullptr, 512, 256, 0, 0, 0, 0);
    relu_ln_kernel<<<NT, 256>>>(x2_, ln2_g, ln2_b, x2_, 0, 0);
    // 4. Mamba: LN+transpose+split -> xn; in_proj GEMM; silu
    ln_seq_split<<<NT, 256>>>(mbln_g, mbln_b);
    split_wT<<<(256 * 1024 + 255) / 256, 256>>>(in_w, 256, 1024);
    gemm3x<<<dim3(8, NT / 128), 128, GEMM_SMEM>>>(
        xh_, xl_, wh_, wl_, in_b, xp_, nullptr, nullptr, 256, 1024, 0, 0, 0, 0);
    silu_kernel<<<(NT * EDIM) / 256, 256>>>();
    // 5. small projections + dt softplus
    transpose_w3<<<(EDIM * DTR + 255) / 256, 256>>>(delta_w, Bp_w, Cp_w);
    proj3_kernel<<<NT / 16, 256>>>(delta_b, Bp_b, Cp_b);
    dtsp_kernel<<<(NT * EDIM) / 256, 256>>>(dt_w, dt_b);
    // 6. scan (writes y split into c1h/c1l)
    scan_kernel<<<NNODE, EDIM>>>(A_log, D_vec);
    // 7. out projection + residual -> outs; split for q/k
    split_wT<<<(512 * 256 + 255) / 256, 256>>>(out_w, 512, 256);
    gemm3x<<<dim3(2, NT / 128), 128, GEMM_SMEM>>>(
        c1h_, c1l_, wh_, wl_, out_b, mb_, nullptr, nullptr, 512, 256, 0, 0, 0, 0);
    write_outs_split<<<NT, 256>>>(outs);
    // 8. q/k GEMMs with bf16-split epilogue, then fused score head
    split_wT<<<(256 * 256 + 255) / 256, 256>>>(q_w, 256, 256);
    gemm3x<<<dim3(2, NT / 128), 128, GEMM_SMEM>>>(
        xh_, xl_, wh_, wl_, nullptr, qh_, ql_, nullptr, 256, 256, 2, 0, 0, 0);
    split_wT<<<(256 * 256 + 255) / 256, 256>>>(k_w, 256, 256);
    gemm3x<<<dim3(2, NT / 128), 128, GEMM_SMEM>>>(
        xh_, xl_, wh_, wl_, nullptr, kh_, kl_, nullptr, 256, 256, 2, 0, 0, 0);
    gemm3x<<<dim3(8, 8, TSTEP), 128, GEMM_SMEM>>>(
        qh_, ql_, kh_, kl_, nullptr, probs, logits, gate_b, 256, 1024, 1,
        (size_t)NNODE * HDIM, (size_t)NNODE * HDIM, (size_t)NNODE * NNODE);
}

// round 10
// speedup vs baseline: 1.7402x; 1.0865x over previous
#include <cuda_runtime.h>
#include <cuda_fp16.h>
#include <cuda_bf16.h>
#include <cstdint>

// Problem constants
#define NNODE 1024
#define TSTEP 32
#define HDIM  256
#define PDIM  256
#define EDIM  512
#define DTR   16
#define SDIM  16
#define NT    (NNODE * TSTEP)   // 32768

#define SMEM_SWIZZLE_128B(byte_offset) \
    ((byte_offset) ^ (((byte_offset) >> 3) & 0x70))

typedef unsigned short ush;

// ===========================================================================
// Scratch (device globals)
// ===========================================================================
__device__ float g_pe    [NNODE * PDIM];
__device__ float g_m1    [NNODE * HDIM];
__device__ float g_pebase[NNODE * HDIM];
__device__ float g_x     [(size_t)NT * HDIM];
__device__ float g_m2    [(size_t)NT * HDIM];
__device__ float g_x2    [(size_t)NT * HDIM];
__device__ float g_xp    [(size_t)NT * 1024];
__device__ float g_x1    [(size_t)NT * EDIM];
__device__ float g_delta [(size_t)NT * EDIM];
__device__ float g_d1    [(size_t)NT * DTR];
__device__ float g_Bm    [(size_t)NT * SDIM];
__device__ float g_Cm    [(size_t)NT * SDIM];
__device__ float g_mb    [(size_t)NT * HDIM];
__device__ float g_dwT   [DTR * EDIM];
__device__ float g_bwT   [DTR * EDIM];
__device__ float g_cwT   [DTR * EDIM];
// adjacency neighbor lists (built once, used by both aggregations)
__device__ int   g_ncnt  [NT];
__device__ int   g_nidx  [(size_t)NT * NNODE];
// 16-bit operand buffers (bf16 or fp16 bit patterns depending on stage)
__device__ ush g_c1h[(size_t)NT * 512];
__device__ ush g_c1l[(size_t)NT * 512];
__device__ ush g_xh [(size_t)NT * HDIM];
__device__ ush g_xl [(size_t)NT * HDIM];
__device__ ush g_qh [(size_t)NT * HDIM];
__device__ ush g_ql [(size_t)NT * HDIM];
__device__ ush g_kh [(size_t)NT * HDIM];
__device__ ush g_kl [(size_t)NT * HDIM];
__device__ ush g_wh [1024 * 512];
__device__ ush g_wl [1024 * 512];

__device__ __forceinline__ void bsplit16(float v, ush& h, ush& l) {  // bf16
    __nv_bfloat16 hh = __float2bfloat16(v);
    __nv_bfloat16 ll = __float2bfloat16(v - __bfloat162float(hh));
    h = *reinterpret_cast<ush*>(&hh);
    l = *reinterpret_cast<ush*>(&ll);
}
__device__ __forceinline__ void fsplit16(float v, ush& h, ush& l) {  // fp16
    __half hh = __float2half(v);
    __half ll = __float2half(v - __half2float(hh));
    h = *reinterpret_cast<ush*>(&hh);
    l = *reinterpret_cast<ush*>(&ll);
}

// ===========================================================================
// Fast math (FMA-pipe exp)
// ===========================================================================
__device__ __forceinline__ float fast_exp(float x) {
    x = fminf(fmaxf(x, -87.0f), 87.0f);
    float y = x * 1.44269504088896340736f;
    float t = y + 12582912.0f;
    int   e = __float_as_int(t) - 0x4B400000;
    float r = t - 12582912.0f;
    float f = (y - r) * 0.69314718055994530942f;
    float p = 1.3888889e-3f;
    p = fmaf(p, f, 8.3333333e-3f);
    p = fmaf(p, f, 4.1666668e-2f);
    p = fmaf(p, f, 1.6666667e-1f);
    p = fmaf(p, f, 0.5f);
    p = fmaf(p, f, 1.0f);
    p = fmaf(p, f, 1.0f);
    float s = __int_as_float((e + 127) << 23);
    return p * s;
}
__device__ __forceinline__ float fast_sigmoid(float x) {
    return 1.0f / (1.0f + fast_exp(-x));
}
__device__ __forceinline__ float fast_softplus(float x) {
    if (x > 20.0f) return x;
    return log1pf(fast_exp(x));
}

// ===========================================================================
// Warp MMA / async-copy primitives (baseline sm_80+ only)
// ===========================================================================
__device__ __forceinline__ uint32_t smem_u32(const void* p) {
    uint32_t a;
    asm("{ .reg .u64 t; cvta.to.shared.u64 t, %1; cvt.u32.u64 %0, t; }"
        : "=r"(a) : "l"(p));
    return a;
}
__device__ __forceinline__ void ldsm_x4(uint32_t* r, uint32_t addr) {
    asm volatile("ldmatrix.sync.aligned.m8n8.x4.shared.b16 {%0,%1,%2,%3}, [%4];"
        : "=r"(r[0]), "=r"(r[1]), "=r"(r[2]), "=r"(r[3]) : "r"(addr));
}
__device__ __forceinline__ void mma_bf16(float* c, const uint32_t* a,
                                         uint32_t b0, uint32_t b1) {
    asm volatile(
        "mma.sync.aligned.m16n8k16.row.col.f32.bf16.bf16.f32 "
        "{%0,%1,%2,%3}, {%4,%5,%6,%7}, {%8,%9}, {%0,%1,%2,%3};"
        : "+f"(c[0]), "+f"(c[1]), "+f"(c[2]), "+f"(c[3])
        : "r"(a[0]), "r"(a[1]), "r"(a[2]), "r"(a[3]), "r"(b0), "r"(b1));
}
__device__ __forceinline__ void mma_f16(float* c, const uint32_t* a,
                                        uint32_t b0, uint32_t b1) {
    asm volatile(
        "mma.sync.aligned.m16n8k16.row.col.f32.f16.f16.f32 "
        "{%0,%1,%2,%3}, {%4,%5,%6,%7}, {%8,%9}, {%0,%1,%2,%3};"
        : "+f"(c[0]), "+f"(c[1]), "+f"(c[2]), "+f"(c[3])
        : "r"(a[0]), "r"(a[1]), "r"(a[2]), "r"(a[3]), "r"(b0), "r"(b1));
}
__device__ __forceinline__ void cp_async16(uint32_t saddr, const void* gaddr) {
    asm volatile("cp.async.cg.shared.global [%0], [%1], 16;"
        :: "r"(saddr), "l"(gaddr));
}
#define CP_COMMIT()  asm volatile("cp.async.commit_group;" ::: "memory")
#define CP_WAIT(n)   asm volatile("cp.async.wait_group %0;" :: "n"(n) : "memory")

// ===========================================================================
// HMMA split GEMM: C[M,Nc] = A[M,K] @ B[Nc,K]^T (fp32 acc)
// FTAIL=0 (bf16): nseg=3 near-exact: Ah*Bh + Al*Bh + Ah*Bl
// FTAIL=1 (fp16): nseg=2 fast path:  Ah*Bh + Al*Bh  (B single fp16)
// 128x128 CTA tile, 4 warps (2M x 2N), warp tile 64x64, K-chunks of 64,
// 2-stage cp.async pipeline, SW128-swizzled smem. 128 threads.
// mode 0: fp32 out (+bias, +addrow[(row&1023)*Nc+col]);
// mode 1: score head (probs+logits); mode 2: fp16 hi/lo split output.
// ===========================================================================
template<int FTAIL>
__global__ void __launch_bounds__(128, 2) gemm_k(
    const ush* __restrict__ Ah, const ush* __restrict__ Al,
    const ush* __restrict__ Bh, const ush* __restrict__ Bl,
    const float* __restrict__ bias, const float* __restrict__ addrow,
    void* __restrict__ out1, void* __restrict__ out2,
    const float* __restrict__ gb_ptr,
    int K, int Nc, int mode, int nseg,
    size_t aBatch, size_t bBatch, size_t cBatch)
{
    extern __shared__ __align__(16) char smem[];
    const uint32_t sb = smem_u32(smem);
    const int tid = threadIdx.x;
    const int wid = tid >> 5, lane = tid & 31;
    const int wm = wid & 1, wn = wid >> 1;

    const size_t zA = (size_t)blockIdx.z * aBatch;
    const size_t zB = (size_t)blockIdx.z * bBatch;
    // seg 0: Ah*Bh  seg 1: Al*Bh  seg 2: Ah*Bl
    const ush* Aseg[3] = { Ah + zA, Al + zA, Ah + zA };
    const ush* Bseg[3] = { Bh + zB, Bh + zB, Bl + zB };

    const int m0 = blockIdx.y * 128, n0 = blockIdx.x * 128;
    const int ksub = K >> 6;
    const int nk = nseg * ksub;

    float acc[4][8][4];
#pragma unroll
    for (int i = 0; i < 4; i++)
#pragma unroll
        for (int j = 0; j < 8; j++)
#pragma unroll
            for (int r = 0; r < 4; r++) acc[i][j][r] = 0.0f;

    const int a_r = ((lane >> 3) & 1) * 8 + (lane & 7);
    const int a_c = ((lane >> 4) & 1) * 8;
    const int b_n = ((lane >> 4) & 1) * 8 + (lane & 7);
    const int b_k = ((lane >> 3) & 1) * 8;

    auto load_tile = [&](const ush* g, int row0, int k0, uint32_t sdst) {
#pragma unroll
        for (int j = 0; j < 8; j++) {
            int c = tid + j * 128;          // 0..1023
            int row = c >> 3, ch = c & 7;
            const void* gp = g + (size_t)(row0 + row) * K + k0 + ch * 8;
            uint32_t sp = sdst + SMEM_SWIZZLE_128B((uint32_t)(row * 128 + ch * 16));
            cp_async16(sp, gp);
        }
    };

    load_tile(Aseg[0], m0, 0, sb);
    load_tile(Bseg[0], n0, 0, sb + 16384);
    CP_COMMIT();

    for (int i = 0; i < nk; i++) {
        int b = i & 1;
        if (i + 1 < nk) {
            int seg = (i + 1) / ksub;
            int k0 = ((i + 1) - seg * ksub) << 6;
            uint32_t sd = sb + (uint32_t)(b ^ 1) * 32768u;
            load_tile(Aseg[seg], m0, k0, sd);
            load_tile(Bseg[seg], n0, k0, sd + 16384);
            CP_COMMIT();
            CP_WAIT(1);
        } else {
            CP_COMMIT();
            CP_WAIT(0);
        }
        __syncthreads();

        uint32_t abase = sb + (uint32_t)b * 32768u;
        uint32_t bbase = abase + 16384u;
#pragma unroll
        for (int ks = 0; ks < 4; ks++) {
            uint32_t afr[4][4];
#pragma unroll
            for (int mi = 0; mi < 4; mi++) {
                int row = wm * 64 + mi * 16 + a_r;
                int col = ks * 16 + a_c;
                ldsm_x4(afr[mi],
                        abase + SMEM_SWIZZLE_128B((uint32_t)(row * 128 + col * 2)));
            }
            uint32_t bfr[4][4];
#pragma unroll
            for (int j = 0; j < 4; j++) {
                int n = wn * 64 + j * 16 + b_n;
                int kc = ks * 16 + b_k;
                ldsm_x4(bfr[j],
                        bbase + SMEM_SWIZZLE_128B((uint32_t)(n * 128 + kc * 2)));
            }
#pragma unroll
            for (int mi = 0; mi < 4; mi++)
#pragma unroll
                for (int ni = 0; ni < 8; ni++) {
                    const uint32_t* bs = bfr[ni >> 1];
                    if (FTAIL)
                        mma_f16(acc[mi][ni], afr[mi],
                                bs[(ni & 1) * 2], bs[(ni & 1) * 2 + 1]);
                    else
                        mma_bf16(acc[mi][ni], afr[mi],
                                 bs[(ni & 1) * 2], bs[(ni & 1) * 2 + 1]);
                }
        }
        __syncthreads();
    }

    // ---------------- epilogue ----------------
    const int rg = lane >> 2;
    const int cg = (lane & 3) * 2;
#pragma unroll
    for (int mi = 0; mi < 4; mi++) {
#pragma unroll
        for (int ni = 0; ni < 8; ni++) {
            float* c = acc[mi][ni];
            int gr0 = m0 + wm * 64 + mi * 16 + rg;
            int gc  = n0 + wn * 64 + ni * 8 + cg;
            if (mode == 0) {
                float* C = (float*)out1;
                float b0 = bias ? bias[gc] : 0.0f;
                float b1 = bias ? bias[gc + 1] : 0.0f;
                if (addrow) {
                    b0 += addrow[(size_t)(gr0 & 1023) * Nc + gc];
                    b1 += addrow[(size_t)(gr0 & 1023) * Nc + gc + 1];
                }
                float b2 = bias ? bias[gc] : 0.0f;
                float b3 = bias ? bias[gc + 1] : 0.0f;
                if (addrow) {
                    b2 += addrow[(size_t)((gr0 + 8) & 1023) * Nc + gc];
                    b3 += addrow[(size_t)((gr0 + 8) & 1023) * Nc + gc + 1];
                }
                *(float2*)(C + (size_t)gr0 * Nc + gc)       = {c[0] + b0, c[1] + b1};
                *(float2*)(C + (size_t)(gr0 + 8) * Nc + gc) = {c[2] + b2, c[3] + b3};
            } else if (mode == 1) {
                float gb = *gb_ptr;
                float* P = (float*)out1 + (size_t)blockIdx.z * cBatch;
                float* L = (float*)out2 + (size_t)blockIdx.z * cBatch;
                float l0 = c[0] * 0.0625f + gb, l1 = c[1] * 0.0625f + gb;
                float l2 = c[2] * 0.0625f + gb, l3 = c[3] * 0.0625f + gb;
                *(float2*)(L + (size_t)gr0 * Nc + gc)       = {l0, l1};
                *(float2*)(L + (size_t)(gr0 + 8) * Nc + gc) = {l2, l3};
                *(float2*)(P + (size_t)gr0 * Nc + gc)       =
                    {fast_sigmoid(l0), fast_sigmoid(l1)};
                *(float2*)(P + (size_t)(gr0 + 8) * Nc + gc) =
                    {fast_sigmoid(l2), fast_sigmoid(l3)};
            } else {  // mode 2: fp16 hi/lo split output
                ush* H  = (ush*)out1;
                ush* Lo = (ush*)out2;
                ush h0, l0, h1, l1;
                fsplit16(c[0], h0, l0); fsplit16(c[1], h1, l1);
                H [(size_t)gr0 * Nc + gc]     = h0; H [(size_t)gr0 * Nc + gc + 1] = h1;
                Lo[(size_t)gr0 * Nc + gc]     = l0; Lo[(size_t)gr0 * Nc + gc + 1] = l1;
                fsplit16(c[2], h0, l0); fsplit16(c[3], h1, l1);
                H [(size_t)(gr0 + 8) * Nc + gc]     = h0;
                H [(size_t)(gr0 + 8) * Nc + gc + 1] = h1;
                Lo[(size_t)(gr0 + 8) * Nc + gc]     = l0;
                Lo[(size_t)(gr0 + 8) * Nc + gc + 1] = l1;
            }
        }
    }
}

// ===========================================================================
// Small SIMT SGEMM (tiny m1 = pe @ msg1_w only) — exact fp32 (R6-validated)
// ===========================================================================
__global__ void __launch_bounds__(256) sgemm_nn(
    const float* __restrict__ A, const float* __restrict__ B,
    const float* __restrict__ bias, float* __restrict__ C,
    int M, int Nc, int K)
{
    __shared__ float As[8][128];
    __shared__ float Bs[8][128];
    int tid = threadIdx.x;
    int bx = blockIdx.x, by = blockIdx.y;
    int tx = tid & 15, ty = tid >> 4;
    int arow = tid >> 1, acol = (tid & 1) * 4;
    int brow = tid >> 5, bcol = (tid & 31) * 4;
    const float* Ab = A + (size_t)by * 128 * K;
    const float* Bb = B + (size_t)bx * 128;
    float acc[8][8] = {};
    for (int k0 = 0; k0 < K; k0 += 8) {
        float4 av = *(const float4*)(Ab + (size_t)arow * K + k0 + acol);
        As[acol + 0][arow] = av.x; As[acol + 1][arow] = av.y;
        As[acol + 2][arow] = av.z; As[acol + 3][arow] = av.w;
        *(float4*)&Bs[brow][bcol] =
            *(const float4*)(Bb + (size_t)(k0 + brow) * Nc + bcol);
        __syncthreads();
#pragma unroll
        for (int kk = 0; kk < 8; kk++) {
            float4 a0 = *(float4*)&As[kk][ty * 8];
            float4 a1 = *(float4*)&As[kk][ty * 8 + 4];
            float4 b0 = *(float4*)&Bs[kk][tx * 8];
            float4 b1 = *(float4*)&Bs[kk][tx * 8 + 4];
            float ar[8] = {a0.x, a0.y, a0.z, a0.w, a1.x, a1.y, a1.z, a1.w};
            float br[8] = {b0.x, b0.y, b0.z, b0.w, b1.x, b1.y, b1.z, b1.w};
#pragma unroll
            for (int i = 0; i < 8; i++)
#pragma unroll
                for (int j = 0; j < 8; j++)
                    acc[i][j] = fmaf(ar[i], br[j], acc[i][j]);
        }
        __syncthreads();
    }
#pragma unroll
    for (int i = 0; i < 8; i++) {
        int r = by * 128 + ty * 8 + i;
#pragma unroll
        for (int j = 0; j < 8; j += 4) {
            int c = bx * 128 + tx * 8 + j;
            float4 v;
            v.x = acc[i][j] + bias[c];         v.y = acc[i][j + 1] + bias[c + 1];
            v.z = acc[i][j + 2] + bias[c + 2]; v.w = acc[i][j + 3] + bias[c + 3];
            *(float4*)(C + (size_t)r * Nc + c) = v;
        }
    }
}

// ===========================================================================
// Elementwise / helper kernels
// ===========================================================================
__global__ void pe_kernel() {
    int n = blockIdx.x;
    int i = threadIdx.x;  // 0..127
    float div = expf((float)(2 * i) * (-0.03597867333f));
    float ang = (float)n * div;
    g_pe[n * PDIM + 2 * i]     = sinf(ang);
    g_pe[n * PDIM + 2 * i + 1] = cosf(ang);
}

// pe split to bf16 (into g_qh/g_ql scratch, 1024 rows) for the one-time GEMM
__global__ void pe_split_bf16() {
    int r = blockIdx.x;            // node
    int c = threadIdx.x;           // 0..255
    ush h, l; bsplit16(g_pe[(size_t)r * PDIM + c], h, l);
    g_qh[(size_t)r * HDIM + c] = h;
    g_ql[(size_t)r * HDIM + c] = l;
}

// weight transpose+split: W[K,N] fp32 -> g_wh/g_wl [N,K]
// dt: 0 = bf16 hi+lo, 1 = fp16 hi only
__global__ void split_wT(const float* __restrict__ W, int K, int N, int dt) {
    int i = blockIdx.x * 256 + threadIdx.x;
    if (i < K * N) {
        int k = i / N, n = i % N;
        if (dt == 0) {
            ush h, l; bsplit16(W[i], h, l);
            g_wh[(size_t)n * K + k] = h;
            g_wl[(size_t)n * K + k] = l;
        } else {
            __half hh = __float2half(W[i]);
            g_wh[(size_t)n * K + k] = *reinterpret_cast<ush*>(&hh);
        }
    }
}

// Build adjacency neighbor lists once (both agg calls share adj)
__global__ void build_nbr(const float* __restrict__ adj) {
    int i = blockIdx.x, t = blockIdx.y;
    size_t row = (size_t)t * NNODE + i;
    const float4* a4 = (const float4*)(adj + row * NNODE);
    __shared__ int s_idx[NNODE];
    __shared__ int s_cnt;
    if (threadIdx.x == 0) s_cnt = 0;
    __syncthreads();
    float4 v = a4[threadIdx.x];
    int j0 = threadIdx.x * 4;
    if (v.x != 0.0f) s_idx[atomicAdd(&s_cnt, 1)] = j0;
    if (v.y != 0.0f) s_idx[atomicAdd(&s_cnt, 1)] = j0 + 1;
    if (v.z != 0.0f) s_idx[atomicAdd(&s_cnt, 1)] = j0 + 2;
    if (v.w != 0.0f) s_idx[atomicAdd(&s_cnt, 1)] = j0 + 3;
    __syncthreads();
    int cnt = s_cnt;
    if (threadIdx.x == 0) g_ncnt[row] = cnt;
    for (int p = threadIdx.x; p < cnt; p += 256)
        g_nidx[row * NNODE + p] = s_idx[p];
}

// Gather aggregation (fp32 exact), bf16 split into dh/dl[row*stride + h]
__global__ void agg_gather(const float* __restrict__ m, int per_t,
                           ush* __restrict__ dh, ush* __restrict__ dl,
                           int stride) {
    int i = blockIdx.x, t = blockIdx.y;
    size_t row = (size_t)t * NNODE + i;
    int cnt = g_ncnt[row];
    const int* idx = g_nidx + row * NNODE;
    int h = threadIdx.x;
    const float* mb = m + (per_t ? (size_t)t * NNODE * HDIM : 0);
    float acc = 0.0f;
    for (int p = 0; p < cnt; p++)
        acc += mb[(size_t)idx[p] * HDIM + h];
    ush hi, lo; bsplit16(acc, hi, lo);
    dh[row * stride + h] = hi;
    dl[row * stride + h] = lo;
}

// ReLU + LN; optional bf16 splits to xh/xl and/or c-buffer cols [0,256)
__global__ void relu_ln_kernel(const float* __restrict__ in,
                               const float* __restrict__ gam,
                               const float* __restrict__ bet,
                               float* __restrict__ out,
                               int to_xhl, int to_cbuf)
{
    int row = blockIdx.x, tid = threadIdx.x;
    float v = fmaxf(in[(size_t)row * HDIM + tid], 0.0f);
    float s = v, q = v * v;
#pragma unroll
    for (int o = 16; o > 0; o >>= 1) {
        s += __shfl_xor_sync(0xffffffffu, s, o);
        q += __shfl_xor_sync(0xffffffffu, q, o);
    }
    __shared__ float ss[8], qq[8];
    __shared__ float s_mu, s_rstd;
    int w = tid >> 5;
    if ((tid & 31) == 0) { ss[w] = s; qq[w] = q; }
    __syncthreads();
    if (tid == 0) {
        float S = 0, QQ = 0;
        for (int i = 0; i < 8; i++) { S += ss[i]; QQ += qq[i]; }
        float mu = S * (1.0f / 256.0f);
        float var = QQ * (1.0f / 256.0f) - mu * mu;
        s_mu = mu; s_rstd = rsqrtf(var + 1e-5f);
    }
    __syncthreads();
    float o = (v - s_mu) * s_rstd * gam[tid] + bet[tid];
    out[(size_t)row * HDIM + tid] = o;
    ush h, l; bsplit16(o, h, l);
    if (to_xhl) {
        g_xh[(size_t)row * HDIM + tid] = h;
        g_xl[(size_t)row * HDIM + tid] = l;
    }
    if (to_cbuf) {
        size_t id = (size_t)row * 512 + tid;
        g_c1h[id] = h; g_c1l[id] = l;
    }
}

// Mamba pre-LN: read x2 (t-major), write bf16 splits xn (n-major)
__global__ void ln_seq_split(const float* __restrict__ gam,
                             const float* __restrict__ bet)
{
    int rin = blockIdx.x;              // t*N + n
    int tid = threadIdx.x;
    int t = rin >> 10, n = rin & 1023;
    float v = g_x2[(size_t)rin * HDIM + tid];
    float s = v, q = v * v;
#pragma unroll
    for (int o = 16; o > 0; o >>= 1) {
        s += __shfl_xor_sync(0xffffffffu, s, o);
        q += __shfl_xor_sync(0xffffffffu, q, o);
    }
    __shared__ float ss[8], qq[8];
    __shared__ float s_mu, s_rstd;
    int w = tid >> 5;
    if ((tid & 31) == 0) { ss[w] = s; qq[w] = q; }
    __syncthreads();
    if (tid == 0) {
        float S = 0, QQ = 0;
        for (int i = 0; i < 8; i++) { S += ss[i]; QQ += qq[i]; }
        float mu = S * (1.0f / 256.0f);
        float var = QQ * (1.0f / 256.0f) - mu * mu;
        s_mu = mu; s_rstd = rsqrtf(var + 1e-5f);
    }
    __syncthreads();
    float o = (v - s_mu) * s_rstd * gam[tid] + bet[tid];
    size_t dst = ((size_t)n * TSTEP + t) * HDIM + tid;
    ush h, l; bsplit16(o, h, l);
    g_xh[dst] = h; g_xl[dst] = l;
}

__global__ void silu_kernel() {
    size_t id = (size_t)blockIdx.x * 256 + threadIdx.x;  // NT*512
    size_t r = id >> 9, e = id & 511;
    float v = g_xp[r * 1024 + e];
    g_x1[id] = v * fast_sigmoid(v);
}

__global__ void transpose_w3(const float* __restrict__ dw,
                             const float* __restrict__ bw,
                             const float* __restrict__ cw)
{
    int id = blockIdx.x * 256 + threadIdx.x;  // 8192
    if (id < EDIM * DTR) {
        int k = id >> 4, n = id & 15;
        g_dwT[n * EDIM + k] = dw[id];
        g_bwT[n * EDIM + k] = bw[id];
        g_cwT[n * EDIM + k] = cw[id];
    }
}

__global__ void proj3_kernel(const float* __restrict__ db,
                             const float* __restrict__ bb,
                             const float* __restrict__ cb)
{
    int r = blockIdx.x * 16 + (threadIdx.x >> 4);
    int n = threadIdx.x & 15;
    const float4* a4 = (const float4*)(g_x1 + (size_t)r * EDIM);
    const float4* d4 = (const float4*)(g_dwT + n * EDIM);
    const float4* b4 = (const float4*)(g_bwT + n * EDIM);
    const float4* c4 = (const float4*)(g_cwT + n * EDIM);
    float ad = 0, ab = 0, ac = 0;
#pragma unroll 4
    for (int k = 0; k < EDIM / 4; k++) {
        float4 a = a4[k];
        float4 d = d4[k], b = b4[k], c = c4[k];
        ad = fmaf(a.x, d.x, fmaf(a.y, d.y, fmaf(a.z, d.z, fmaf(a.w, d.w, ad))));
        ab = fmaf(a.x, b.x, fmaf(a.y, b.y, fmaf(a.z, b.z, fmaf(a.w, b.w, ab))));
        ac = fmaf(a.x, c.x, fmaf(a.y, c.y, fmaf(a.z, c.z, fmaf(a.w, c.w, ac))));
    }
    size_t o = (size_t)r * 16 + n;
    g_d1[o] = ad + db[n];
    g_Bm[o] = ab + bb[n];
    g_Cm[o] = ac + cb[n];
}

__global__ void dtsp_kernel(const float* __restrict__ dtw,
                            const float* __restrict__ dtb)
{
    size_t id = (size_t)blockIdx.x * 256 + threadIdx.x;  // NT*512
    size_t r = id >> 9;
    int e = (int)(id & 511);
    const float* d1r = g_d1 + r * 16;
    float acc = dtb[e];
#pragma unroll
    for (int k = 0; k < 16; k++)
        acc = fmaf(d1r[k], dtw[k * EDIM + e], acc);
    g_delta[id] = fast_softplus(acc);
}

// Selective scan; B/C preloaded; writes y as fp16 splits into g_c1h/g_c1l
__global__ void __launch_bounds__(512) scan_kernel(
    const float* __restrict__ A_log, const float* __restrict__ D_vec)
{
    int n = blockIdx.x;
    int e = threadIdx.x;
    float A[SDIM], h[SDIM];
#pragma unroll
    for (int s = 0; s < SDIM; s++) {
        A[s] = -fast_exp(A_log[e * SDIM + s]);
        h[s] = 0.0f;
    }
    float Dv = D_vec[e];
    __shared__ float sbv[TSTEP * SDIM], scv[TSTEP * SDIM];
    sbv[e] = g_Bm[(size_t)n * (TSTEP * SDIM) + e];
    scv[e] = g_Cm[(size_t)n * (TSTEP * SDIM) + e];
    __syncthreads();
    for (int t = 0; t < TSTEP; t++) {
        size_t r = (size_t)n * TSTEP + t;
        const float* sb = sbv + t * SDIM;
        const float* sc = scv + t * SDIM;
        float dt = g_delta[r * EDIM + e];
        float xt = g_x1[r * EDIM + e];
        float dx = dt * xt;
        float yv = 0.0f;
#pragma unroll
        for (int s = 0; s < SDIM; s++) {
            h[s] = fmaf(fast_exp(dt * A[s]), h[s], dx * sb[s]);
            yv   = fmaf(sc[s], h[s], yv);
        }
        yv += xt * Dv;
        float g = g_xp[r * 1024 + EDIM + e];
        yv *= g * fast_sigmoid(g);
        ush hi, lo; fsplit16(yv, hi, lo);
        g_c1h[r * EDIM + e] = hi;
        g_c1l[r * EDIM + e] = lo;
    }
}

// outs = mb (n-major) + x2 (t-major); fp16 splits for q/k GEMM input
__global__ void write_outs_split(float* __restrict__ outs) {
    int ro = blockIdx.x;               // t*N + n
    int tid = threadIdx.x;
    int t = ro >> 10, n = ro & 1023;
    float v = g_mb[((size_t)n * TSTEP + t) * HDIM + tid]
            + g_x2[(size_t)ro * HDIM + tid];
    size_t dst = (size_t)ro * HDIM + tid;
    outs[dst] = v;
    ush h, l; fsplit16(v, h, l);
    g_xh[dst] = h; g_xl[dst] = l;
}

// ===========================================================================
// Host launch
// ===========================================================================
#define GEMM_SMEM 65536

extern "C" void kernel_launch(void* const* d_in, const int* in_sizes, int n_in,
                              void* d_out, int out_size)
{
    const float* adj     = (const float*)d_in[0];
    const float* msg1_w  = (const float*)d_in[1];
    const float* msg1_b  = (const float*)d_in[2];
    const float* upd1_w  = (const float*)d_in[3];
    const float* upd1_b  = (const float*)d_in[4];
    const float* ln1_g   = (const float*)d_in[5];
    const float* ln1_b   = (const float*)d_in[6];
    const float* msg2_w  = (const float*)d_in[7];
    const float* msg2_b  = (const float*)d_in[8];
    const float* upd2_w  = (const float*)d_in[9];
    const float* upd2_b  = (const float*)d_in[10];
    const float* ln2_g   = (const float*)d_in[11];
    const float* ln2_b   = (const float*)d_in[12];
    const float* mbln_g  = (const float*)d_in[13];
    const float* mbln_b  = (const float*)d_in[14];
    const float* in_w    = (const float*)d_in[15];
    const float* in_b    = (const float*)d_in[16];
    const float* delta_w = (const float*)d_in[17];
    const float* delta_b = (const float*)d_in[18];
    const float* dt_w    = (const float*)d_in[19];
    const float* dt_b    = (const float*)d_in[20];
    const float* Bp_w    = (const float*)d_in[21];
    const float* Bp_b    = (const float*)d_in[22];
    const float* Cp_w    = (const float*)d_in[23];
    const float* Cp_b    = (const float*)d_in[24];
    const float* A_log   = (const float*)d_in[25];
    const float* D_vec   = (const float*)d_in[26];
    const float* out_w   = (const float*)d_in[27];
    const float* out_b   = (const float*)d_in[28];
    const float* q_w     = (const float*)d_in[29];
    const float* k_w     = (const float*)d_in[30];
    const float* gate_b  = (const float*)d_in[31];

    float* out    = (float*)d_out;
    float* outs   = out;                                    // [T,N,H]
    float* probs  = out + (size_t)TSTEP * NNODE * HDIM;     // [T,N,N]
    float* logits = probs + (size_t)TSTEP * NNODE * NNODE;  // [T,N,N]

    cudaFuncSetAttribute(gemm_k<0>, cudaFuncAttributeMaxDynamicSharedMemorySize,
                         GEMM_SMEM);
    cudaFuncSetAttribute(gemm_k<1>, cudaFuncAttributeMaxDynamicSharedMemorySize,
                         GEMM_SMEM);

    float *pe_, *m1_, *pebase_, *x_, *m2_, *x2_, *xp_, *mb_;
    ush *c1h_, *c1l_, *xh_, *xl_, *qh_, *ql_, *kh_, *kl_, *wh_, *wl_;
    cudaGetSymbolAddress((void**)&pe_,     g_pe);
    cudaGetSymbolAddress((void**)&m1_,     g_m1);
    cudaGetSymbolAddress((void**)&pebase_, g_pebase);
    cudaGetSymbolAddress((void**)&x_,      g_x);
    cudaGetSymbolAddress((void**)&m2_,     g_m2);
    cudaGetSymbolAddress((void**)&x2_,     g_x2);
    cudaGetSymbolAddress((void**)&xp_,     g_xp);
    cudaGetSymbolAddress((void**)&mb_,     g_mb);
    cudaGetSymbolAddress((void**)&c1h_,    g_c1h);
    cudaGetSymbolAddress((void**)&c1l_,    g_c1l);
    cudaGetSymbolAddress((void**)&xh_,     g_xh);
    cudaGetSymbolAddress((void**)&xl_,     g_xl);
    cudaGetSymbolAddress((void**)&qh_,     g_qh);
    cudaGetSymbolAddress((void**)&ql_,     g_ql);
    cudaGetSymbolAddress((void**)&kh_,     g_kh);
    cudaGetSymbolAddress((void**)&kl_,     g_kl);
    cudaGetSymbolAddress((void**)&wh_,     g_wh);
    cudaGetSymbolAddress((void**)&wl_,     g_wl);

    // 1. PE + neighbor lists + m1 (exact SIMT GEMM)
    pe_kernel<<<NNODE, 128>>>();
    build_nbr<<<dim3(NNODE, TSTEP), 256>>>(adj);
    sgemm_nn<<<dim3(HDIM / 128, NNODE / 128), 256>>>(pe_, msg1_w, msg1_b, m1_,
                                                     NNODE, HDIM, PDIM);
    // 2. upd1 factorized: pebase = pe @ W_top + b (once, t-invariant);
    //    x = agg1 @ W_bot + pebase[n]
    pe_split_bf16<<<NNODE, 256>>>();
    split_wT<<<(256 * 256 + 255) / 256, 256>>>(upd1_w, 256, 256, 0);  // W_top
    gemm_k<0><<<dim3(2, NNODE / 128), 128, GEMM_SMEM>>>(
        qh_, ql_, wh_, wl_, upd1_b, nullptr, pebase_, nullptr, nullptr,
        256, 256, 0, 3, 0, 0, 0);
    agg_gather<<<dim3(NNODE, TSTEP), 256>>>(m1_, 0, xh_, xl_, 256);
    split_wT<<<(256 * 256 + 255) / 256, 256>>>(upd1_w + 256 * 256, 256, 256, 0);
    gemm_k<0><<<dim3(2, NT / 128), 128, GEMM_SMEM>>>(
        xh_, xl_, wh_, wl_, nullptr, pebase_, x_, nullptr, nullptr,
        256, 256, 0, 3, 0, 0, 0);
    relu_ln_kernel<<<NT, 256>>>(x_, ln1_g, ln1_b, x_, 1, 1);
    // 3. layer 2: m2 GEMM; agg2 into c-buffer; upd2 GEMM; relu+LN
    split_wT<<<(256 * 256 + 255) / 256, 256>>>(msg2_w, 256, 256, 0);
    gemm_k<0><<<dim3(2, NT / 128), 128, GEMM_SMEM>>>(
        xh_, xl_, wh_, wl_, msg2_b, nullptr, m2_, nullptr, nullptr,
        256, 256, 0, 3, 0, 0, 0);
    agg_gather<<<dim3(NNODE, TSTEP), 256>>>(m2_, 1, c1h_ + 256, c1l_ + 256, 512);
    split_wT<<<(512 * 256 + 255) / 256, 256>>>(upd2_w, 512, 256, 0);
    gemm_k<0><<<dim3(2, NT / 128), 128, GEMM_SMEM>>>(
        c1h_, c1l_, wh_, wl_, upd2_b, nullptr, x2_, nullptr, nullptr,
        512, 256, 0, 3, 0, 0, 0);
    relu_ln_kernel<<<NT, 256>>>(x2_, ln2_g, ln2_b, x2_, 0, 0);
    // 4. Mamba: LN+transpose -> xh/xl; in_proj GEMM; silu
    ln_seq_split<<<NT, 256>>>(mbln_g, mbln_b);
    split_wT<<<(256 * 1024 + 255) / 256, 256>>>(in_w, 256, 1024, 0);
    gemm_k<0><<<dim3(8, NT / 128), 128, GEMM_SMEM>>>(
        xh_, xl_, wh_, wl_, in_b, nullptr, xp_, nullptr, nullptr,
        256, 1024, 0, 3, 0, 0, 0);
    silu_kernel<<<(NT * EDIM) / 256, 256>>>();
    // 5. small projections + dt softplus (exact)
    transpose_w3<<<(EDIM * DTR + 255) / 256, 256>>>(delta_w, Bp_w, Cp_w);
    proj3_kernel<<<NT / 16, 256>>>(delta_b, Bp_b, Cp_b);
    dtsp_kernel<<<(NT * EDIM) / 256, 256>>>(dt_w, dt_b);
    // 6. scan (writes y fp16 splits into c1h/c1l)
    scan_kernel<<<NNODE, EDIM>>>(A_log, D_vec);
    // 7. out projection (fp16 2-pass) + residual -> outs; fp16 splits for q/k
    split_wT<<<(512 * 256 + 255) / 256, 256>>>(out_w, 512, 256, 1);
    gemm_k<1><<<dim3(2, NT / 128), 128, GEMM_SMEM>>>(
        c1h_, c1l_, wh_, nullptr, out_b, nullptr, mb_, nullptr, nullptr,
        512, 256, 0, 2, 0, 0, 0);
    write_outs_split<<<NT, 256>>>(outs);
    // 8. q/k GEMMs (fp16 2-pass, split outputs), then score head (fp16 2-pass)
    split_wT<<<(256 * 256 + 255) / 256, 256>>>(q_w, 256, 256, 1);
    gemm_k<1><<<dim3(2, NT / 128), 128, GEMM_SMEM>>>(
        xh_, xl_, wh_, nullptr, nullptr, nullptr, qh_, ql_, nullptr,
        256, 256, 2, 2, 0, 0, 0);
    split_wT<<<(256 * 256 + 255) / 256, 256>>>(k_w, 256, 256, 1);
    gemm_k<1><<<dim3(2, NT / 128), 128, GEMM_SMEM>>>(
        xh_, xl_, wh_, nullptr, nullptr, nullptr, kh_, kl_, nullptr,
        256, 256, 2, 2, 0, 0, 0);
    gemm_k<1><<<dim3(8, 8, TSTEP), 128, GEMM_SMEM>>>(
        qh_, ql_, kh_, kl_, nullptr, nullptr, probs, logits, gate_b,
        256, 1024, 1, 2,
        (size_t)NNODE * HDIM, (size_t)NNODE * HDIM, (size_t)NNODE * NNODE);
}

// round 12
// speedup vs baseline: 1.7760x; 1.0205x over previous
#include <cuda_runtime.h>
#include <cuda_fp16.h>
#include <cuda_bf16.h>
#include <cstdint>

// Problem constants
#define NNODE 1024
#define TSTEP 32
#define HDIM  256
#define PDIM  256
#define EDIM  512
#define DTR   16
#define SDIM  16
#define NT    (NNODE * TSTEP)   // 32768

#define SMEM_SWIZZLE_128B(byte_offset) \
    ((byte_offset) ^ (((byte_offset) >> 3) & 0x70))

typedef unsigned short ush;

// ===========================================================================
// Scratch (device globals)
// ===========================================================================
__device__ float g_pe    [NNODE * PDIM];
__device__ float g_m1    [NNODE * HDIM];
__device__ float g_pebase[NNODE * HDIM];
__device__ float g_x     [(size_t)NT * HDIM];
__device__ float g_m2    [(size_t)NT * HDIM];
__device__ float g_x2    [(size_t)NT * HDIM];
__device__ float g_xp    [(size_t)NT * 1024];
__device__ float g_delta [(size_t)NT * EDIM];
__device__ float g_d1    [(size_t)NT * DTR];
__device__ float g_Bm    [(size_t)NT * SDIM];
__device__ float g_Cm    [(size_t)NT * SDIM];
__device__ float g_dwT   [DTR * EDIM];
__device__ float g_bwT   [DTR * EDIM];
__device__ float g_cwT   [DTR * EDIM];
// adjacency neighbor lists (built once, used by both aggregations)
__device__ int   g_ncnt  [NT];
__device__ int   g_nidx  [(size_t)NT * NNODE];
// 16-bit operand buffers (bf16 or fp16 bit patterns depending on stage)
__device__ ush g_c1h[(size_t)NT * 512];
__device__ ush g_c1l[(size_t)NT * 512];
__device__ ush g_xh [(size_t)NT * HDIM];
__device__ ush g_xl [(size_t)NT * HDIM];
__device__ ush g_qh [(size_t)NT * HDIM];
__device__ ush g_ql [(size_t)NT * HDIM];
__device__ ush g_kh [(size_t)NT * HDIM];
__device__ ush g_wh [1024 * 512];
__device__ ush g_wl [1024 * 512];

__device__ __forceinline__ void bsplit16(float v, ush& h, ush& l) {  // bf16
    __nv_bfloat16 hh = __float2bfloat16(v);
    __nv_bfloat16 ll = __float2bfloat16(v - __bfloat162float(hh));
    h = *reinterpret_cast<ush*>(&hh);
    l = *reinterpret_cast<ush*>(&ll);
}
__device__ __forceinline__ void fsplit16(float v, ush& h, ush& l) {  // fp16
    __half hh = __float2half(v);
    __half ll = __float2half(v - __half2float(hh));
    h = *reinterpret_cast<ush*>(&hh);
    l = *reinterpret_cast<ush*>(&ll);
}
__device__ __forceinline__ ush f2h16(float v) {
    __half hh = __float2half(v);
    return *reinterpret_cast<ush*>(&hh);
}

// ===========================================================================
// Fast math (FMA-pipe exp)
// ===========================================================================
__device__ __forceinline__ float fast_exp(float x) {
    x = fminf(fmaxf(x, -87.0f), 87.0f);
    float y = x * 1.44269504088896340736f;
    float t = y + 12582912.0f;
    int   e = __float_as_int(t) - 0x4B400000;
    float r = t - 12582912.0f;
    float f = (y - r) * 0.69314718055994530942f;
    float p = 1.3888889e-3f;
    p = fmaf(p, f, 8.3333333e-3f);
    p = fmaf(p, f, 4.1666668e-2f);
    p = fmaf(p, f, 1.6666667e-1f);
    p = fmaf(p, f, 0.5f);
    p = fmaf(p, f, 1.0f);
    p = fmaf(p, f, 1.0f);
    float s = __int_as_float((e + 127) << 23);
    return p * s;
}
__device__ __forceinline__ float fast_sigmoid(float x) {
    return 1.0f / (1.0f + fast_exp(-x));
}
__device__ __forceinline__ float fast_softplus(float x) {
    if (x > 20.0f) return x;
    return log1pf(fast_exp(x));
}

// ===========================================================================
// Warp MMA / async-copy primitives (baseline sm_80+ only)
// ===========================================================================
__device__ __forceinline__ uint32_t smem_u32(const void* p) {
    uint32_t a;
    asm("{ .reg .u64 t; cvta.to.shared.u64 t, %1; cvt.u32.u64 %0, t; }"
        : "=r"(a) : "l"(p));
    return a;
}
__device__ __forceinline__ void ldsm_x4(uint32_t* r, uint32_t addr) {
    asm volatile("ldmatrix.sync.aligned.m8n8.x4.shared.b16 {%0,%1,%2,%3}, [%4];"
        : "=r"(r[0]), "=r"(r[1]), "=r"(r[2]), "=r"(r[3]) : "r"(addr));
}
__device__ __forceinline__ void mma_bf16(float* c, const uint32_t* a,
                                         uint32_t b0, uint32_t b1) {
    asm volatile(
        "mma.sync.aligned.m16n8k16.row.col.f32.bf16.bf16.f32 "
        "{%0,%1,%2,%3}, {%4,%5,%6,%7}, {%8,%9}, {%0,%1,%2,%3};"
        : "+f"(c[0]), "+f"(c[1]), "+f"(c[2]), "+f"(c[3])
        : "r"(a[0]), "r"(a[1]), "r"(a[2]), "r"(a[3]), "r"(b0), "r"(b1));
}
__device__ __forceinline__ void mma_f16(float* c, const uint32_t* a,
                                        uint32_t b0, uint32_t b1) {
    asm volatile(
        "mma.sync.aligned.m16n8k16.row.col.f32.f16.f16.f32 "
        "{%0,%1,%2,%3}, {%4,%5,%6,%7}, {%8,%9}, {%0,%1,%2,%3};"
        : "+f"(c[0]), "+f"(c[1]), "+f"(c[2]), "+f"(c[3])
        : "r"(a[0]), "r"(a[1]), "r"(a[2]), "r"(a[3]), "r"(b0), "r"(b1));
}
__device__ __forceinline__ void cp_async16(uint32_t saddr, const void* gaddr) {
    asm volatile("cp.async.cg.shared.global [%0], [%1], 16;"
        :: "r"(saddr), "l"(gaddr));
}
#define CP_COMMIT()  asm volatile("cp.async.commit_group;" ::: "memory")
#define CP_WAIT(n)   asm volatile("cp.async.wait_group %0;" :: "n"(n) : "memory")

// ===========================================================================
// HMMA split GEMM: C[M,Nc] = A[M,K] @ B[Nc,K]^T (fp32 acc)
// FTAIL=0 (bf16, nseg=3 near-exact) / FTAIL=1 (fp16; nseg=2 or 1)
// seg 0: Ah*Bh   seg 1: Al*Bh   seg 2: Ah*Bl
// 128x128 CTA tile, 4 warps (2M x 2N), warp tile 64x64, K-chunks of 64,
// 2-stage cp.async pipeline, SW128-swizzled smem. 128 threads.
// mode 0: fp32 out (+bias, +addrow[(row&1023)*Nc+col])
// mode 1: score head (probs+logits)
// mode 2: fp16 output (hi only)
// mode 3: out_proj fused epilogue — rows n-major (r=n*32+t); writes
//         outs[(t*N+n)*Nc+c] = acc + bias + addrow[same]  (fp32, out1)
//         and fp16 copy to out2 at the same index.
// ===========================================================================
template<int FTAIL>
__global__ void __launch_bounds__(128, 2) gemm_k(
    const ush* __restrict__ Ah, const ush* __restrict__ Al,
    const ush* __restrict__ Bh, const ush* __restrict__ Bl,
    const float* __restrict__ bias, const float* __restrict__ addrow,
    void* __restrict__ out1, void* __restrict__ out2,
    const float* __restrict__ gb_ptr,
    int K, int Nc, int mode, int nseg,
    size_t aBatch, size_t bBatch, size_t cBatch)
{
    extern __shared__ __align__(16) char smem[];
    const uint32_t sb = smem_u32(smem);
    const int tid = threadIdx.x;
    const int wid = tid >> 5, lane = tid & 31;
    const int wm = wid & 1, wn = wid >> 1;

    const size_t zA = (size_t)blockIdx.z * aBatch;
    const size_t zB = (size_t)blockIdx.z * bBatch;
    const ush* Aseg[3] = { Ah + zA, Al + zA, Ah + zA };
    const ush* Bseg[3] = { Bh + zB, Bh + zB, Bl + zB };

    const int m0 = blockIdx.y * 128, n0 = blockIdx.x * 128;
    const int ksub = K >> 6;
    const int nk = nseg * ksub;

    float acc[4][8][4];
#pragma unroll
    for (int i = 0; i < 4; i++)
#pragma unroll
        for (int j = 0; j < 8; j++)
#pragma unroll
            for (int r = 0; r < 4; r++) acc[i][j][r] = 0.0f;

    const int a_r = ((lane >> 3) & 1) * 8 + (lane & 7);
    const int a_c = ((lane >> 4) & 1) * 8;
    const int b_n = ((lane >> 4) & 1) * 8 + (lane & 7);
    const int b_k = ((lane >> 3) & 1) * 8;

    auto load_tile = [&](const ush* g, int row0, int k0, uint32_t sdst) {
#pragma unroll
        for (int j = 0; j < 8; j++) {
            int c = tid + j * 128;          // 0..1023
            int row = c >> 3, ch = c & 7;
            const void* gp = g + (size_t)(row0 + row) * K + k0 + ch * 8;
            uint32_t sp = sdst + SMEM_SWIZZLE_128B((uint32_t)(row * 128 + ch * 16));
            cp_async16(sp, gp);
        }
    };

    load_tile(Aseg[0], m0, 0, sb);
    load_tile(Bseg[0], n0, 0, sb + 16384);
    CP_COMMIT();

    for (int i = 0; i < nk; i++) {
        int b = i & 1;
        if (i + 1 < nk) {
            int seg = (i + 1) / ksub;
            int k0 = ((i + 1) - seg * ksub) << 6;
            uint32_t sd = sb + (uint32_t)(b ^ 1) * 32768u;
            load_tile(Aseg[seg], m0, k0, sd);
            load_tile(Bseg[seg], n0, k0, sd + 16384);
            CP_COMMIT();
            CP_WAIT(1);
        } else {
            CP_COMMIT();
            CP_WAIT(0);
        }
        __syncthreads();

        uint32_t abase = sb + (uint32_t)b * 32768u;
        uint32_t bbase = abase + 16384u;
#pragma unroll
        for (int ks = 0; ks < 4; ks++) {
            uint32_t afr[4][4];
#pragma unroll
            for (int mi = 0; mi < 4; mi++) {
                int row = wm * 64 + mi * 16 + a_r;
                int col = ks * 16 + a_c;
                ldsm_x4(afr[mi],
                        abase + SMEM_SWIZZLE_128B((uint32_t)(row * 128 + col * 2)));
            }
            uint32_t bfr[4][4];
#pragma unroll
            for (int j = 0; j < 4; j++) {
                int n = wn * 64 + j * 16 + b_n;
                int kc = ks * 16 + b_k;
                ldsm_x4(bfr[j],
                        bbase + SMEM_SWIZZLE_128B((uint32_t)(n * 128 + kc * 2)));
            }
#pragma unroll
            for (int mi = 0; mi < 4; mi++)
#pragma unroll
                for (int ni = 0; ni < 8; ni++) {
                    const uint32_t* bs = bfr[ni >> 1];
                    if (FTAIL)
                        mma_f16(acc[mi][ni], afr[mi],
                                bs[(ni & 1) * 2], bs[(ni & 1) * 2 + 1]);
                    else
                        mma_bf16(acc[mi][ni], afr[mi],
                                 bs[(ni & 1) * 2], bs[(ni & 1) * 2 + 1]);
                }
        }
        __syncthreads();
    }

    // ---------------- epilogue ----------------
    const int rg = lane >> 2;
    const int cg = (lane & 3) * 2;
#pragma unroll
    for (int mi = 0; mi < 4; mi++) {
#pragma unroll
        for (int ni = 0; ni < 8; ni++) {
            float* c = acc[mi][ni];
            int gr0 = m0 + wm * 64 + mi * 16 + rg;
            int gc  = n0 + wn * 64 + ni * 8 + cg;
            if (mode == 0) {
                float* C = (float*)out1;
                float b0 = bias ? bias[gc] : 0.0f;
                float b1 = bias ? bias[gc + 1] : 0.0f;
                if (addrow) {
                    b0 += addrow[(size_t)(gr0 & 1023) * Nc + gc];
                    b1 += addrow[(size_t)(gr0 & 1023) * Nc + gc + 1];
                }
                float b2 = bias ? bias[gc] : 0.0f;
                float b3 = bias ? bias[gc + 1] : 0.0f;
                if (addrow) {
                    b2 += addrow[(size_t)((gr0 + 8) & 1023) * Nc + gc];
                    b3 += addrow[(size_t)((gr0 + 8) & 1023) * Nc + gc + 1];
                }
                *(float2*)(C + (size_t)gr0 * Nc + gc)       = {c[0] + b0, c[1] + b1};
                *(float2*)(C + (size_t)(gr0 + 8) * Nc + gc) = {c[2] + b2, c[3] + b3};
            } else if (mode == 1) {
                float gb = *gb_ptr;
                float* P = (float*)out1 + (size_t)blockIdx.z * cBatch;
                float* L = (float*)out2 + (size_t)blockIdx.z * cBatch;
                float l0 = c[0] * 0.0625f + gb, l1 = c[1] * 0.0625f + gb;
                float l2 = c[2] * 0.0625f + gb, l3 = c[3] * 0.0625f + gb;
                *(float2*)(L + (size_t)gr0 * Nc + gc)       = {l0, l1};
                *(float2*)(L + (size_t)(gr0 + 8) * Nc + gc) = {l2, l3};
                *(float2*)(P + (size_t)gr0 * Nc + gc)       =
                    {fast_sigmoid(l0), fast_sigmoid(l1)};
                *(float2*)(P + (size_t)(gr0 + 8) * Nc + gc) =
                    {fast_sigmoid(l2), fast_sigmoid(l3)};
            } else if (mode == 2) {  // fp16 output (hi only)
                ush* H = (ush*)out1;
                H[(size_t)gr0 * Nc + gc]           = f2h16(c[0]);
                H[(size_t)gr0 * Nc + gc + 1]       = f2h16(c[1]);
                H[(size_t)(gr0 + 8) * Nc + gc]     = f2h16(c[2]);
                H[(size_t)(gr0 + 8) * Nc + gc + 1] = f2h16(c[3]);
            } else {  // mode 3: out_proj fused residual + transpose + fp16 copy
                float* O = (float*)out1;
                ush*   H = (ush*)out2;
                int t0 = gr0 & 31, nn0 = gr0 >> 5;
                size_t d0 = ((size_t)t0 * NNODE + nn0) * Nc + gc;
                float v0 = c[0] + bias[gc]     + addrow[d0];
                float v1 = c[1] + bias[gc + 1] + addrow[d0 + 1];
                *(float2*)(O + d0) = {v0, v1};
                H[d0] = f2h16(v0); H[d0 + 1] = f2h16(v1);
                int t1 = (gr0 + 8) & 31, nn1 = (gr0 + 8) >> 5;
                size_t d1 = ((size_t)t1 * NNODE + nn1) * Nc + gc;
                float v2 = c[2] + bias[gc]     + addrow[d1];
                float v3 = c[3] + bias[gc + 1] + addrow[d1 + 1];
                *(float2*)(O + d1) = {v2, v3};
                H[d1] = f2h16(v2); H[d1 + 1] = f2h16(v3);
            }
        }
    }
}

// ===========================================================================
// Small SIMT SGEMM (tiny m1 = pe @ msg1_w only) — exact fp32
// ===========================================================================
__global__ void __launch_bounds__(256) sgemm_nn(
    const float* __restrict__ A, const float* __restrict__ B,
    const float* __restrict__ bias, float* __restrict__ C,
    int M, int Nc, int K)
{
    __shared__ float As[8][128];
    __shared__ float Bs[8][128];
    int tid = threadIdx.x;
    int bx = blockIdx.x, by = blockIdx.y;
    int tx = tid & 15, ty = tid >> 4;
    int arow = tid >> 1, acol = (tid & 1) * 4;
    int brow = tid >> 5, bcol = (tid & 31) * 4;
    const float* Ab = A + (size_t)by * 128 * K;
    const float* Bb = B + (size_t)bx * 128;
    float acc[8][8] = {};
    for (int k0 = 0; k0 < K; k0 += 8) {
        float4 av = *(const float4*)(Ab + (size_t)arow * K + k0 + acol);
        As[acol + 0][arow] = av.x; As[acol + 1][arow] = av.y;
        As[acol + 2][arow] = av.z; As[acol + 3][arow] = av.w;
        *(float4*)&Bs[brow][bcol] =
            *(const float4*)(Bb + (size_t)(k0 + brow) * Nc + bcol);
        __syncthreads();
#pragma unroll
        for (int kk = 0; kk < 8; kk++) {
            float4 a0 = *(float4*)&As[kk][ty * 8];
            float4 a1 = *(float4*)&As[kk][ty * 8 + 4];
            float4 b0 = *(float4*)&Bs[kk][tx * 8];
            float4 b1 = *(float4*)&Bs[kk][tx * 8 + 4];
            float ar[8] = {a0.x, a0.y, a0.z, a0.w, a1.x, a1.y, a1.z, a1.w};
            float br[8] = {b0.x, b0.y, b0.z, b0.w, b1.x, b1.y, b1.z, b1.w};
#pragma unroll
            for (int i = 0; i < 8; i++)
#pragma unroll
                for (int j = 0; j < 8; j++)
                    acc[i][j] = fmaf(ar[i], br[j], acc[i][j]);
        }
        __syncthreads();
    }
#pragma unroll
    for (int i = 0; i < 8; i++) {
        int r = by * 128 + ty * 8 + i;
#pragma unroll
        for (int j = 0; j < 8; j += 4) {
            int c = bx * 128 + tx * 8 + j;
            float4 v;
            v.x = acc[i][j] + bias[c];         v.y = acc[i][j + 1] + bias[c + 1];
            v.z = acc[i][j + 2] + bias[c + 2]; v.w = acc[i][j + 3] + bias[c + 3];
            *(float4*)(C + (size_t)r * Nc + c) = v;
        }
    }
}

// ===========================================================================
// Elementwise / helper kernels
// ===========================================================================
__global__ void pe_kernel() {
    int n = blockIdx.x;
    int i = threadIdx.x;  // 0..127
    float div = expf((float)(2 * i) * (-0.03597867333f));
    float ang = (float)n * div;
    g_pe[n * PDIM + 2 * i]     = sinf(ang);
    g_pe[n * PDIM + 2 * i + 1] = cosf(ang);
}

// pe split to bf16 (into g_qh/g_ql scratch, 1024 rows) for the one-time GEMM
__global__ void pe_split_bf16() {
    int r = blockIdx.x;            // node
    int c = threadIdx.x;           // 0..255
    ush h, l; bsplit16(g_pe[(size_t)r * PDIM + c], h, l);
    g_qh[(size_t)r * HDIM + c] = h;
    g_ql[(size_t)r * HDIM + c] = l;
}

// weight transpose+split: W[K,N] fp32 -> g_wh/g_wl [N,K]
// dt: 0 = bf16 hi+lo, 1 = fp16 hi only
__global__ void split_wT(const float* __restrict__ W, int K, int N, int dt) {
    int i = blockIdx.x * 256 + threadIdx.x;
    if (i < K * N) {
        int k = i / N, n = i % N;
        if (dt == 0) {
            ush h, l; bsplit16(W[i], h, l);
            g_wh[(size_t)n * K + k] = h;
            g_wl[(size_t)n * K + k] = l;
        } else {
            g_wh[(size_t)n * K + k] = f2h16(W[i]);
        }
    }
}

// Build adjacency neighbor lists once (both agg calls share adj)
__global__ void build_nbr(const float* __restrict__ adj) {
    int i = blockIdx.x, t = blockIdx.y;
    size_t row = (size_t)t * NNODE + i;
    const float4* a4 = (const float4*)(adj + row * NNODE);
    __shared__ int s_idx[NNODE];
    __shared__ int s_cnt;
    if (threadIdx.x == 0) s_cnt = 0;
    __syncthreads();
    float4 v = a4[threadIdx.x];
    int j0 = threadIdx.x * 4;
    if (v.x != 0.0f) s_idx[atomicAdd(&s_cnt, 1)] = j0;
    if (v.y != 0.0f) s_idx[atomicAdd(&s_cnt, 1)] = j0 + 1;
    if (v.z != 0.0f) s_idx[atomicAdd(&s_cnt, 1)] = j0 + 2;
    if (v.w != 0.0f) s_idx[atomicAdd(&s_cnt, 1)] = j0 + 3;
    __syncthreads();
    int cnt = s_cnt;
    if (threadIdx.x == 0) g_ncnt[row] = cnt;
    for (int p = threadIdx.x; p < cnt; p += 256)
        g_nidx[row * NNODE + p] = s_idx[p];
}

// Gather aggregation (fp32 exact), bf16 split into dh/dl[row*stride + h]
__global__ void agg_gather(const float* __restrict__ m, int per_t,
                           ush* __restrict__ dh, ush* __restrict__ dl,
                           int stride) {
    int i = blockIdx.x, t = blockIdx.y;
    size_t row = (size_t)t * NNODE + i;
    int cnt = g_ncnt[row];
    const int* idx = g_nidx + row * NNODE;
    int h = threadIdx.x;
    const float* mb = m + (per_t ? (size_t)t * NNODE * HDIM : 0);
    float acc = 0.0f;
    for (int p = 0; p < cnt; p++)
        acc += mb[(size_t)idx[p] * HDIM + h];
    ush hi, lo; bsplit16(acc, hi, lo);
    dh[row * stride + h] = hi;
    dl[row * stride + h] = lo;
}

// ReLU + LN; optional bf16 splits to xh/xl and/or c-buffer cols [0,256)
__global__ void relu_ln_kernel(const float* __restrict__ in,
                               const float* __restrict__ gam,
                               const float* __restrict__ bet,
                               float* __restrict__ out,
                               int to_xhl, int to_cbuf)
{
    int row = blockIdx.x, tid = threadIdx.x;
    float v = fmaxf(in[(size_t)row * HDIM + tid], 0.0f);
    float s = v, q = v * v;
#pragma unroll
    for (int o = 16; o > 0; o >>= 1) {
        s += __shfl_xor_sync(0xffffffffu, s, o);
        q += __shfl_xor_sync(0xffffffffu, q, o);
    }
    __shared__ float ss[8], qq[8];
    __shared__ float s_mu, s_rstd;
    int w = tid >> 5;
    if ((tid & 31) == 0) { ss[w] = s; qq[w] = q; }
    __syncthreads();
    if (tid == 0) {
        float S = 0, QQ = 0;
        for (int i = 0; i < 8; i++) { S += ss[i]; QQ += qq[i]; }
        float mu = S * (1.0f / 256.0f);
        float var = QQ * (1.0f / 256.0f) - mu * mu;
        s_mu = mu; s_rstd = rsqrtf(var + 1e-5f);
    }
    __syncthreads();
    float o = (v - s_mu) * s_rstd * gam[tid] + bet[tid];
    out[(size_t)row * HDIM + tid] = o;
    ush h, l; bsplit16(o, h, l);
    if (to_xhl) {
        g_xh[(size_t)row * HDIM + tid] = h;
        g_xl[(size_t)row * HDIM + tid] = l;
    }
    if (to_cbuf) {
        size_t id = (size_t)row * 512 + tid;
        g_c1h[id] = h; g_c1l[id] = l;
    }
}

// Mamba pre-LN: read x2 (t-major), write bf16 splits xn (n-major)
__global__ void ln_seq_split(const float* __restrict__ gam,
                             const float* __restrict__ bet)
{
    int rin = blockIdx.x;              // t*N + n
    int tid = threadIdx.x;
    int t = rin >> 10, n = rin & 1023;
    float v = g_x2[(size_t)rin * HDIM + tid];
    float s = v, q = v * v;
#pragma unroll
    for (int o = 16; o > 0; o >>= 1) {
        s += __shfl_xor_sync(0xffffffffu, s, o);
        q += __shfl_xor_sync(0xffffffffu, q, o);
    }
    __shared__ float ss[8], qq[8];
    __shared__ float s_mu, s_rstd;
    int w = tid >> 5;
    if ((tid & 31) == 0) { ss[w] = s; qq[w] = q; }
    __syncthreads();
    if (tid == 0) {
        float S = 0, QQ = 0;
        for (int i = 0; i < 8; i++) { S += ss[i]; QQ += qq[i]; }
        float mu = S * (1.0f / 256.0f);
        float var = QQ * (1.0f / 256.0f) - mu * mu;
        s_mu = mu; s_rstd = rsqrtf(var + 1e-5f);
    }
    __syncthreads();
    float o = (v - s_mu) * s_rstd * gam[tid] + bet[tid];
    size_t dst = ((size_t)n * TSTEP + t) * HDIM + tid;
    ush h, l; bsplit16(o, h, l);
    g_xh[dst] = h; g_xl[dst] = l;
}

__global__ void transpose_w3(const float* __restrict__ dw,
                             const float* __restrict__ bw,
                             const float* __restrict__ cw)
{
    int id = blockIdx.x * 256 + threadIdx.x;  // 8192
    if (id < EDIM * DTR) {
        int k = id >> 4, n = id & 15;
        g_dwT[n * EDIM + k] = dw[id];
        g_bwT[n * EDIM + k] = bw[id];
        g_cwT[n * EDIM + k] = cw[id];
    }
}

// proj3 with inline silu on xp (x1 never materialized)
__global__ void proj3_kernel(const float* __restrict__ db,
                             const float* __restrict__ bb,
                             const float* __restrict__ cb)
{
    int r = blockIdx.x * 16 + (threadIdx.x >> 4);
    int n = threadIdx.x & 15;
    const float4* a4 = (const float4*)(g_xp + (size_t)r * 1024);
    const float4* d4 = (const float4*)(g_dwT + n * EDIM);
    const float4* b4 = (const float4*)(g_bwT + n * EDIM);
    const float4* c4 = (const float4*)(g_cwT + n * EDIM);
    float ad = 0, ab = 0, ac = 0;
#pragma unroll 4
    for (int k = 0; k < EDIM / 4; k++) {
        float4 a = a4[k];
        a.x *= fast_sigmoid(a.x); a.y *= fast_sigmoid(a.y);
        a.z *= fast_sigmoid(a.z); a.w *= fast_sigmoid(a.w);
        float4 d = d4[k], b = b4[k], c = c4[k];
        ad = fmaf(a.x, d.x, fmaf(a.y, d.y, fmaf(a.z, d.z, fmaf(a.w, d.w, ad))));
        ab = fmaf(a.x, b.x, fmaf(a.y, b.y, fmaf(a.z, b.z, fmaf(a.w, b.w, ab))));
        ac = fmaf(a.x, c.x, fmaf(a.y, c.y, fmaf(a.z, c.z, fmaf(a.w, c.w, ac))));
    }
    size_t o = (size_t)r * 16 + n;
    g_d1[o] = ad + db[n];
    g_Bm[o] = ab + bb[n];
    g_Cm[o] = ac + cb[n];
}

__global__ void dtsp_kernel(const float* __restrict__ dtw,
                            const float* __restrict__ dtb)
{
    size_t id = (size_t)blockIdx.x * 256 + threadIdx.x;  // NT*512
    size_t r = id >> 9;
    int e = (int)(id & 511);
    const float* d1r = g_d1 + r * 16;
    float acc = dtb[e];
#pragma unroll
    for (int k = 0; k < 16; k++)
        acc = fmaf(d1r[k], dtw[k * EDIM + e], acc);
    g_delta[id] = fast_softplus(acc);
}

// Selective scan; inline silu on xp; B/C preloaded;
// writes y as fp16 splits into g_c1h/g_c1l
__global__ void __launch_bounds__(512) scan_kernel(
    const float* __restrict__ A_log, const float* __restrict__ D_vec)
{
    int n = blockIdx.x;
    int e = threadIdx.x;
    float A[SDIM], h[SDIM];
#pragma unroll
    for (int s = 0; s < SDIM; s++) {
        A[s] = -fast_exp(A_log[e * SDIM + s]);
        h[s] = 0.0f;
    }
    float Dv = D_vec[e];
    __shared__ float sbv[TSTEP * SDIM], scv[TSTEP * SDIM];
    sbv[e] = g_Bm[(size_t)n * (TSTEP * SDIM) + e];
    scv[e] = g_Cm[(size_t)n * (TSTEP * SDIM) + e];
    __syncthreads();
    for (int t = 0; t < TSTEP; t++) {
        size_t r = (size_t)n * TSTEP + t;
        const float* sb = sbv + t * SDIM;
        const float* sc = scv + t * SDIM;
        float dt = g_delta[r * EDIM + e];
        float xv = g_xp[r * 1024 + e];
        float xt = xv * fast_sigmoid(xv);
        float dx = dt * xt;
        float yv = 0.0f;
#pragma unroll
        for (int s = 0; s < SDIM; s++) {
            h[s] = fmaf(fast_exp(dt * A[s]), h[s], dx * sb[s]);
            yv   = fmaf(sc[s], h[s], yv);
        }
        yv += xt * Dv;
        float g = g_xp[r * 1024 + EDIM + e];
        yv *= g * fast_sigmoid(g);
        ush hi, lo; fsplit16(yv, hi, lo);
        g_c1h[r * EDIM + e] = hi;
        g_c1l[r * EDIM + e] = lo;
    }
}

// ===========================================================================
// Host launch
// ===========================================================================
#define GEMM_SMEM 65536

extern "C" void kernel_launch(void* const* d_in, const int* in_sizes, int n_in,
                              void* d_out, int out_size)
{
    const float* adj     = (const float*)d_in[0];
    const float* msg1_w  = (const float*)d_in[1];
    const float* msg1_b  = (const float*)d_in[2];
    const float* upd1_w  = (const float*)d_in[3];
    const float* upd1_b  = (const float*)d_in[4];
    const float* ln1_g   = (const float*)d_in[5];
    const float* ln1_b   = (const float*)d_in[6];
    const float* msg2_w  = (const float*)d_in[7];
    const float* msg2_b  = (const float*)d_in[8];
    const float* upd2_w  = (const float*)d_in[9];
    const float* upd2_b  = (const float*)d_in[10];
    const float* ln2_g   = (const float*)d_in[11];
    const float* ln2_b   = (const float*)d_in[12];
    const float* mbln_g  = (const float*)d_in[13];
    const float* mbln_b  = (const float*)d_in[14];
    const float* in_w    = (const float*)d_in[15];
    const float* in_b    = (const float*)d_in[16];
    const float* delta_w = (const float*)d_in[17];
    const float* delta_b = (const float*)d_in[18];
    const float* dt_w    = (const float*)d_in[19];
    const float* dt_b    = (const float*)d_in[20];
    const float* Bp_w    = (const float*)d_in[21];
    const float* Bp_b    = (const float*)d_in[22];
    const float* Cp_w    = (const float*)d_in[23];
    const float* Cp_b    = (const float*)d_in[24];
    const float* A_log   = (const float*)d_in[25];
    const float* D_vec   = (const float*)d_in[26];
    const float* out_w   = (const float*)d_in[27];
    const float* out_b   = (const float*)d_in[28];
    const float* q_w     = (const float*)d_in[29];
    const float* k_w     = (const float*)d_in[30];
    const float* gate_b  = (const float*)d_in[31];

    float* out    = (float*)d_out;
    float* outs   = out;                                    // [T,N,H]
    float* probs  = out + (size_t)TSTEP * NNODE * HDIM;     // [T,N,N]
    float* logits = probs + (size_t)TSTEP * NNODE * NNODE;  // [T,N,N]

    cudaFuncSetAttribute(gemm_k<0>, cudaFuncAttributeMaxDynamicSharedMemorySize,
                         GEMM_SMEM);
    cudaFuncSetAttribute(gemm_k<1>, cudaFuncAttributeMaxDynamicSharedMemorySize,
                         GEMM_SMEM);

    float *pe_, *m1_, *pebase_, *x_, *m2_, *x2_, *xp_;
    ush *c1h_, *c1l_, *xh_, *xl_, *qh_, *ql_, *kh_, *wh_, *wl_;
    cudaGetSymbolAddress((void**)&pe_,     g_pe);
    cudaGetSymbolAddress((void**)&m1_,     g_m1);
    cudaGetSymbolAddress((void**)&pebase_, g_pebase);
    cudaGetSymbolAddress((void**)&x_,      g_x);
    cudaGetSymbolAddress((void**)&m2_,     g_m2);
    cudaGetSymbolAddress((void**)&x2_,     g_x2);
    cudaGetSymbolAddress((void**)&xp_,     g_xp);
    cudaGetSymbolAddress((void**)&c1h_,    g_c1h);
    cudaGetSymbolAddress((void**)&c1l_,    g_c1l);
    cudaGetSymbolAddress((void**)&xh_,     g_xh);
    cudaGetSymbolAddress((void**)&xl_,     g_xl);
    cudaGetSymbolAddress((void**)&qh_,     g_qh);
    cudaGetSymbolAddress((void**)&ql_,     g_ql);
    cudaGetSymbolAddress((void**)&kh_,     g_kh);
    cudaGetSymbolAddress((void**)&wh_,     g_wh);
    cudaGetSymbolAddress((void**)&wl_,     g_wl);

    // 1. PE + neighbor lists + m1 (exact SIMT GEMM)
    pe_kernel<<<NNODE, 128>>>();
    build_nbr<<<dim3(NNODE, TSTEP), 256>>>(adj);
    sgemm_nn<<<dim3(HDIM / 128, NNODE / 128), 256>>>(pe_, msg1_w, msg1_b, m1_,
                                                     NNODE, HDIM, PDIM);
    // 2. upd1 factorized: pebase = pe @ W_top + b (once, t-invariant);
    //    x = agg1 @ W_bot + pebase[n]
    pe_split_bf16<<<NNODE, 256>>>();
    split_wT<<<(256 * 256 + 255) / 256, 256>>>(upd1_w, 256, 256, 0);  // W_top
    gemm_k<0><<<dim3(2, NNODE / 128), 128, GEMM_SMEM>>>(
        qh_, ql_, wh_, wl_, upd1_b, nullptr, pebase_, nullptr, nullptr,
        256, 256, 0, 3, 0, 0, 0);
    agg_gather<<<dim3(NNODE, TSTEP), 256>>>(m1_, 0, xh_, xl_, 256);
    split_wT<<<(256 * 256 + 255) / 256, 256>>>(upd1_w + 256 * 256, 256, 256, 0);
    gemm_k<0><<<dim3(2, NT / 128), 128, GEMM_SMEM>>>(
        xh_, xl_, wh_, wl_, nullptr, pebase_, x_, nullptr, nullptr,
        256, 256, 0, 3, 0, 0, 0);
    relu_ln_kernel<<<NT, 256>>>(x_, ln1_g, ln1_b, x_, 1, 1);
    // 3. layer 2: m2 GEMM; agg2 into c-buffer; upd2 GEMM; relu+LN
    split_wT<<<(256 * 256 + 255) / 256, 256>>>(msg2_w, 256, 256, 0);
    gemm_k<0><<<dim3(2, NT / 128), 128, GEMM_SMEM>>>(
        xh_, xl_, wh_, wl_, msg2_b, nullptr, m2_, nullptr, nullptr,
        256, 256, 0, 3, 0, 0, 0);
    agg_gather<<<dim3(NNODE, TSTEP), 256>>>(m2_, 1, c1h_ + 256, c1l_ + 256, 512);
    split_wT<<<(512 * 256 + 255) / 256, 256>>>(upd2_w, 512, 256, 0);
    gemm_k<0><<<dim3(2, NT / 128), 128, GEMM_SMEM>>>(
        c1h_, c1l_, wh_, wl_, upd2_b, nullptr, x2_, nullptr, nullptr,
        512, 256, 0, 3, 0, 0, 0);
    relu_ln_kernel<<<NT, 256>>>(x2_, ln2_g, ln2_b, x2_, 0, 0);
    // 4. Mamba: LN+transpose -> xh/xl; in_proj GEMM
    ln_seq_split<<<NT, 256>>>(mbln_g, mbln_b);
    split_wT<<<(256 * 1024 + 255) / 256, 256>>>(in_w, 256, 1024, 0);
    gemm_k<0><<<dim3(8, NT / 128), 128, GEMM_SMEM>>>(
        xh_, xl_, wh_, wl_, in_b, nullptr, xp_, nullptr, nullptr,
        256, 1024, 0, 3, 0, 0, 0);
    // 5. small projections (inline silu) + dt softplus
    transpose_w3<<<(EDIM * DTR + 255) / 256, 256>>>(delta_w, Bp_w, Cp_w);
    proj3_kernel<<<NT / 16, 256>>>(delta_b, Bp_b, Cp_b);
    dtsp_kernel<<<(NT * EDIM) / 256, 256>>>(dt_w, dt_b);
    // 6. scan (inline silu; writes y fp16 splits into c1h/c1l)
    scan_kernel<<<NNODE, EDIM>>>(A_log, D_vec);
    // 7. out projection (fp16 2-pass) with FUSED residual+transpose epilogue:
    //    writes outs (fp32, t-major) and fp16 copy into xh for q/k GEMMs
    split_wT<<<(512 * 256 + 255) / 256, 256>>>(out_w, 512, 256, 1);
    gemm_k<1><<<dim3(2, NT / 128), 128, GEMM_SMEM>>>(
        c1h_, c1l_, wh_, nullptr, out_b, x2_, outs, xh_, nullptr,
        512, 256, 3, 2, 0, 0, 0);
    // 8. q/k GEMMs (fp16 1-pass), then score head (fp16 1-pass)
    split_wT<<<(256 * 256 + 255) / 256, 256>>>(q_w, 256, 256, 1);
    gemm_k<1><<<dim3(2, NT / 128), 128, GEMM_SMEM>>>(
        xh_, nullptr, wh_, nullptr, nullptr, nullptr, qh_, nullptr, nullptr,
        256, 256, 2, 1, 0, 0, 0);
    split_wT<<<(256 * 256 + 255) / 256, 256>>>(k_w, 256, 256, 1);
    gemm_k<1><<<dim3(2, NT / 128), 128, GEMM_SMEM>>>(
        xh_, nullptr, wh_, nullptr, nullptr, nullptr, kh_, nullptr, nullptr,
        256, 256, 2, 1, 0, 0, 0);
    gemm_k<1><<<dim3(8, 8, TSTEP), 128, GEMM_SMEM>>>(
        qh_, nullptr, kh_, nullptr, nullptr, nullptr, probs, logits, gate_b,
        256, 1024, 1, 1,
        (size_t)NNODE * HDIM, (size_t)NNODE * HDIM, (size_t)NNODE * NNODE);
}